// round 6
// baseline (speedup 1.0000x reference)
#include <cuda_runtime.h>
#include <cuda_bf16.h>
#include <cstdint>

#define MAXN 32768
#define MAXE 32768
#define MEM  150
#define JPAD 512

// Column layout (j in [0,512)):
//   j in [0,480):   gate g = j/160, m = j%160; valid if m<150 -> GRU row g*150+m
//                   (g=0: z, g=1: r, g=2: htilde)
//   j in [480,500): attention row q = j-480
//   else pad (zero weights/bias)

// ---------------- static device scratch (no allocations allowed) ------------
__device__ float g_state[MAXN * MEM];            // merged K/H per node
__device__ float g_stat [MAXN * JPAD];           // per-node static: Ww@w + Wt@tag + bias
__device__ float g_rel  [MAXN * JPAD];           // per-node: Wrel@rel
__device__ float g_leafpre[MAXN * JPAD];         // leaf GRU pre-activations
__device__ float g_gate[(size_t)MAXE * JPAD];    // per-edge activated gates (z,r,ht)
__device__ float g_WcombT[320 * JPAD];           // [w|tag] static weights, i-major
__device__ float g_leafWT [320 * JPAD];          // leaf_W transposed, i-major
__device__ float g_WrelT  [20  * JPAD];
__device__ float4 g_dyn4[76 * JPAD];             // dyn weights: vi 0..149=U(h), 152..301=Wk(k)
__device__ float g_bias[JPAD];
__device__ float g_c0[JPAD];                     // leaf: leaf_U@leaf_h + leaf_b
__device__ int   g_edge_done[MAXE];
__device__ int   g_child_ready[MAXN];
__device__ int   g_gflag[3 * MAXE];

// ---------------- sync helpers ----------------
__device__ __forceinline__ int ld_acq(const int* p) {
    int v;
    asm volatile("ld.acquire.gpu.global.b32 %0, [%1];" : "=r"(v) : "l"(p) : "memory");
    return v;
}
__device__ __forceinline__ void st_rel(int* p, int v) {
    asm volatile("st.release.gpu.global.b32 [%0], %1;" :: "l"(p), "r"(v) : "memory");
}
__device__ __forceinline__ float sigf(float x) { return 1.f / (1.f + expf(-x)); }

// column -> (gru row | att row) mapping
__device__ __forceinline__ void colmap(int j, int& row, int& q) {
    row = -1; q = -1;
    if (j < 480) { int m = j % 160; if (m < 150) row = (j / 160) * 150 + m; }
    else if (j < 500) q = j - 480;
}

// ---------------- init ----------------
__global__ void k_init(int N, int E) {
    int stride = gridDim.x * blockDim.x;
    int t0 = blockIdx.x * blockDim.x + threadIdx.x;
    for (int i = t0; i < N * MEM; i += stride) g_state[i] = 0.f;
    for (int i = t0; i < E; i += stride) g_edge_done[i] = 0;
    for (int i = t0; i < 3 * E; i += stride) g_gflag[i] = 0;
    for (int i = t0; i < N; i += stride) g_child_ready[i] = 0;
}

// ---------------- weight reshuffles ----------------
// node_W: (450,490), x layout: [word 0..299 | K 300..449 | rel 450..469 | tag 470..489]
__global__ void k_build_big(const float* __restrict__ node_W, const float* __restrict__ node_U,
                            const float* __restrict__ at_Wb,  const float* __restrict__ leaf_W) {
    int idx = blockIdx.x * blockDim.x + threadIdx.x;
    if (idx >= 320 * JPAD) return;
    int i = idx / JPAD, j = idx % JPAD;
    int row, q; colmap(j, row, q);
    float v = 0.f;
    if (row >= 0)      v = (i < 300) ? node_W[row * 490 + i] : node_W[row * 490 + 470 + (i - 300)];
    else if (q >= 0)   v = (i < 300) ? at_Wb[q * 490 + i]    : at_Wb[q * 490 + 470 + (i - 300)];
    g_WcombT[idx] = v;
    g_leafWT[idx] = (row >= 0) ? leaf_W[row * 320 + i] : 0.f;
    if (i < 304) {
        float mv = 0.f;
        if (i < 150) {
            if (row >= 0) mv = node_U[row * 150 + i];
        } else if (i >= 152 && i < 302) {
            int kk = i - 152;
            if (row >= 0)      mv = node_W[row * 490 + 300 + kk];
            else if (q >= 0)   mv = at_Wb[q * 490 + 300 + kk];
        }
        reinterpret_cast<float*>(g_dyn4)[((i >> 2) * JPAD + j) * 4 + (i & 3)] = mv;
    }
}

__global__ void k_build_small(const float* __restrict__ node_W, const float* __restrict__ at_Wb,
                              const float* __restrict__ node_b, const float* __restrict__ at_bb) {
    int idx = blockIdx.x * blockDim.x + threadIdx.x;
    if (idx < 20 * JPAD) {
        int i = idx / JPAD, j = idx % JPAD;
        int row, q; colmap(j, row, q);
        float v = 0.f;
        if (row >= 0)    v = node_W[row * 490 + 450 + i];
        else if (q >= 0) v = at_Wb[q * 490 + 450 + i];
        g_WrelT[idx] = v;
    } else if (idx < 21 * JPAD) {
        int j = idx - 20 * JPAD;
        int row, q; colmap(j, row, q);
        g_bias[j] = (row >= 0) ? node_b[row] : ((q >= 0) ? at_bb[q] : 0.f);
    }
}

__global__ void k_c0(const float* __restrict__ leaf_U, const float* __restrict__ leaf_h,
                     const float* __restrict__ leaf_b) {
    int j = threadIdx.x;
    if (j >= JPAD) return;
    int row, q; colmap(j, row, q);
    float v = 0.f;
    if (row >= 0) {
        v = leaf_b[row];
        for (int n = 0; n < MEM; n++) v += leaf_U[row * 150 + n] * leaf_h[n];
    }
    g_c0[j] = v;
}

// ---------------- tiled GEMM over [w|tag] (K=320) ----------------
#define BM 64
#define BN 64
#define BK 16
__global__ void __launch_bounds__(256) k_gemm(int mode, int M,
                                              const float* __restrict__ w_emb,
                                              const float* __restrict__ tag_emb,
                                              const int* __restrict__ lids) {
    __shared__ float As[BK][BM + 4];
    __shared__ float Bs[BK][BN];
    const float* B = (mode == 0) ? g_WcombT : g_leafWT;
    int tid = threadIdx.x;
    int tx = tid & 15, ty = tid >> 4;
    int m0 = blockIdx.x * BM, j0 = blockIdx.y * BN;
    int ka = tid & 15, ma = tid >> 4;
    int jb = tid & 63, kb = tid >> 6;
    float acc[4][4] = {};
    for (int k0 = 0; k0 < 320; k0 += BK) {
        #pragma unroll
        for (int it = 0; it < 4; it++) {
            int r = m0 + ma + 16 * it;
            if (r >= M) r = M - 1;
            int row = (mode == 1) ? lids[r] : r;
            int i = k0 + ka;
            As[ka][ma + 16 * it] = (i < 300) ? w_emb[row * 300 + i]
                                             : tag_emb[row * 20 + (i - 300)];
        }
        #pragma unroll
        for (int it = 0; it < 4; it++)
            Bs[kb + 4 * it][jb] = B[(k0 + kb + 4 * it) * JPAD + (j0 + jb)];
        __syncthreads();
        #pragma unroll
        for (int k = 0; k < BK; k++) {
            float4 a4 = *(const float4*)&As[k][ty * 4];
            float4 b4 = *(const float4*)&Bs[k][tx * 4];
            float av[4] = {a4.x, a4.y, a4.z, a4.w};
            float bv[4] = {b4.x, b4.y, b4.z, b4.w};
            #pragma unroll
            for (int mm = 0; mm < 4; mm++)
                #pragma unroll
                for (int jj = 0; jj < 4; jj++)
                    acc[mm][jj] = fmaf(av[mm], bv[jj], acc[mm][jj]);
        }
        __syncthreads();
    }
    #pragma unroll
    for (int mm = 0; mm < 4; mm++) {
        int r = m0 + ty * 4 + mm;
        if (r >= M) continue;
        #pragma unroll
        for (int jj = 0; jj < 4; jj++) {
            int j = j0 + tx * 4 + jj;
            if (mode == 0) g_stat[r * JPAD + j]    = acc[mm][jj] + g_bias[j];
            else           g_leafpre[r * JPAD + j] = acc[mm][jj] + g_c0[j];
        }
    }
}

// ---------------- rel projection (K=20) ----------------
__global__ void __launch_bounds__(512) k_relpart(const float* __restrict__ rel_emb) {
    int n = blockIdx.x, j = threadIdx.x;
    float acc = 0.f;
    #pragma unroll
    for (int q = 0; q < 20; q++)
        acc = fmaf(g_WrelT[q * JPAD + j], __ldg(&rel_emb[n * 20 + q]), acc);
    g_rel[n * JPAD + j] = acc;
}

// ---------------- leaf epilogue ----------------
__global__ void k_leafcomb(const int* __restrict__ lids, const float* __restrict__ leaf_h, int L) {
    int idx = blockIdx.x * blockDim.x + threadIdx.x;
    if (idx >= L * MEM) return;
    int l = idx / MEM, m = idx % MEM;
    float z  = sigf (g_leafpre[l * JPAD + m]);
    float r  = sigf (g_leafpre[l * JPAD + 160 + m]);
    float ht = tanhf(g_leafpre[l * JPAD + 320 + m]);
    g_state[lids[l] * MEM + m] = r * leaf_h[m] + (1.f - z) * ht;
}

__global__ void k_leafready(const int* __restrict__ lids, int L) {
    int l = blockIdx.x * blockDim.x + threadIdx.x;
    if (l < L) g_child_ready[lids[l]] = 1;
}

// ---------------- persistent 4-CTA-group edge kernel (SMEM-resident weights) --
// role 0: z rows (j 0..159)     role 1: r rows (160..319)
// role 2: ht rows (320..479)    role 3: att (480..511) + combine
#define NGROUP 36
#define EDGE_SMEM (1216 + 76 * 160 * 16)

__global__ void __launch_bounds__(160, 1) k_edges(const int* __restrict__ ed, int E, int G,
                                                  const float* __restrict__ at_Wa,
                                                  const float* __restrict__ at_ba) {
    extern __shared__ float smem[];
    float*  vsm = smem;                                        // 304 floats (+pad)
    float4* sw4 = reinterpret_cast<float4*>(smem + 304);       // weight slice
    __shared__ float s_a;
    int tid = threadIdx.x;
    int group = blockIdx.x % G;
    int role  = blockIdx.x / G;
    int ncol = (role == 3) ? 32 : 160;
    int j0   = (role == 3) ? 480 : role * 160;

    // load persistent weight slice
    for (int r = 0; r < 76; r++)
        if (tid < ncol) sw4[r * ncol + tid] = g_dyn4[r * JPAD + j0 + tid];
    __syncthreads();

    float ba = (role == 3) ? *at_ba : 0.f;
    float wa = (role == 3 && tid < 20) ? at_Wa[tid] : 0.f;

    for (int e = group; e < E; e += G) {
        int p = ed[2 * e], c = ed[2 * e + 1];
        bool sib = (e > 0) && (ed[2 * e - 2] == p);
        int j = j0 + tid;

        // prefetch static terms (independent of state)
        float statv = 0.f, relv = 0.f;
        if (tid < ncol) {
            statv = __ldcg(&g_stat[(size_t)p * JPAD + j]);
            relv  = __ldcg(&g_rel [(size_t)c * JPAD + j]);
        }

        // wait child, load k
        if (tid == 0) { int it = 0; while (!ld_acq(&g_child_ready[c])) { if (++it > 64) __nanosleep(20); } }
        __syncthreads();
        if (tid < 152) vsm[152 + tid] = (tid < 150) ? __ldcg(&g_state[c * MEM + tid]) : 0.f;
        // wait sibling, load h
        if (tid == 0 && sib) { int it = 0; while (!ld_acq(&g_edge_done[e - 1])) { if (++it > 64) __nanosleep(20); } }
        __syncthreads();
        if (tid < 152) vsm[tid] = (tid < 150) ? __ldcg(&g_state[p * MEM + tid]) : 0.f;
        __syncthreads();

        float acc = statv + relv;
        if (tid < ncol) {
            const float4* wp = sw4 + tid;
            const float4* vp = reinterpret_cast<const float4*>(vsm);
            #pragma unroll 4
            for (int r = 0; r < 76; r++) {
                float4 w = *wp; wp += ncol;
                float4 v = vp[r];
                acc += w.x * v.x + w.y * v.y + w.z * v.z + w.w * v.w;
            }
        }

        if (role < 3) {
            if (tid < 150) {
                float gv = (role == 2) ? tanhf(acc) : sigf(acc);
                g_gate[(size_t)e * JPAD + j] = gv;
            }
            __syncthreads();
            if (tid == 0) { __threadfence(); st_rel(&g_gflag[role * MAXE + e], 1); }
        } else {
            float av = (tid < 20) ? wa * tanhf(acc) : 0.f;
            if (tid < 32) {
                #pragma unroll
                for (int off = 16; off; off >>= 1) av += __shfl_down_sync(0xffffffffu, av, off);
                if (tid == 0) s_a = sigf(av + ba);
            }
            if (tid == 1) { int it = 0; while (!ld_acq(&g_gflag[e]))            { if (++it > 64) __nanosleep(20); } }
            if (tid == 2) { int it = 0; while (!ld_acq(&g_gflag[MAXE + e]))     { if (++it > 64) __nanosleep(20); } }
            if (tid == 3) { int it = 0; while (!ld_acq(&g_gflag[2 * MAXE + e])) { if (++it > 64) __nanosleep(20); } }
            __syncthreads();
            if (tid < 150) {
                float h  = vsm[tid];
                float z  = __ldcg(&g_gate[(size_t)e * JPAD + tid]);
                float r_ = __ldcg(&g_gate[(size_t)e * JPAD + 160 + tid]);
                float ht = __ldcg(&g_gate[(size_t)e * JPAD + 320 + tid]);
                float m  = r_ * h + (1.f - z) * ht;
                float a  = s_a;
                g_state[p * MEM + tid] = a * m + (1.f - a) * h;
            }
            __syncthreads();
            if (tid == 0) {
                __threadfence();
                st_rel(&g_edge_done[e], 1);
                bool last = (e == E - 1) || (ed[2 * e + 2] != p);
                if (last) st_rel(&g_child_ready[p], 1);
            }
        }
    }
}

__global__ void k_out(float* __restrict__ out) {
    int m = threadIdx.x;
    if (m < MEM) out[m] = g_state[m];
}

// ---------------- launch ----------------
extern "C" void kernel_launch(void* const* d_in, const int* in_sizes, int n_in,
                              void* d_out, int out_size) {
    const float* w_emb   = (const float*)d_in[0];
    const float* tag_emb = (const float*)d_in[1];
    const float* rel_emb = (const float*)d_in[2];
    const float* leaf_h  = (const float*)d_in[3];
    const float* leaf_W  = (const float*)d_in[4];
    const float* leaf_U  = (const float*)d_in[5];
    const float* leaf_b  = (const float*)d_in[6];
    const float* node_W  = (const float*)d_in[7];
    const float* node_U  = (const float*)d_in[8];
    const float* node_b  = (const float*)d_in[9];
    const float* at_Wb   = (const float*)d_in[10];
    const float* at_bb   = (const float*)d_in[11];
    const float* at_Wa   = (const float*)d_in[12];
    const float* at_ba   = (const float*)d_in[13];
    const int*   edges   = (const int*)d_in[14];
    const int*   lids    = (const int*)d_in[15];

    int N = in_sizes[0] / 300;
    int E = in_sizes[14] / 2;
    int L = in_sizes[15];

    cudaFuncSetAttribute(k_edges, cudaFuncAttributeMaxDynamicSharedMemorySize, EDGE_SMEM);

    k_init<<<256, 256>>>(N, E);
    k_build_big<<<(320 * JPAD + 255) / 256, 256>>>(node_W, node_U, at_Wb, leaf_W);
    k_build_small<<<(21 * JPAD + 255) / 256, 256>>>(node_W, at_Wb, node_b, at_bb);
    k_c0<<<1, 512>>>(leaf_U, leaf_h, leaf_b);
    k_gemm<<<dim3((N + BM - 1) / BM, JPAD / BN), 256>>>(0, N, w_emb, tag_emb, lids);
    k_gemm<<<dim3((L + BM - 1) / BM, JPAD / BN), 256>>>(1, L, w_emb, tag_emb, lids);
    k_relpart<<<N, 512>>>(rel_emb);
    k_leafcomb<<<(L * MEM + 255) / 256, 256>>>(lids, leaf_h, L);
    k_leafready<<<(L + 255) / 256, 256>>>(lids, L);
    k_edges<<<4 * NGROUP, 160, EDGE_SMEM>>>(edges, E, NGROUP, at_Wa, at_ba);
    k_out<<<1, 256>>>((float*)d_out);
}

// round 8
// speedup vs baseline: 1.1939x; 1.1939x over previous
#include <cuda_runtime.h>
#include <cuda_bf16.h>
#include <cstdint>

#define MAXN 32768
#define MAXE 32768
#define MEM  150
#define JPAD 512
#define NCLUST 36

// ---- shared-memory byte offsets (same layout in every CTA) ----
#define OFF_TICK 0                  // 2 ints (double-buffered ticket)
#define OFF_SA   8                  // float (role3)
#define OFF_GATE 16                 // 480 floats -> [16,1936)
#define OFF_VSM  1936               // 304 floats -> [1936,3152), 16B aligned
#define OFF_W    3152               // 76*160 float4 = 194560B
#define EDGE_SMEM (OFF_W + 76*160*16)   // 197,712 bytes

// ---------------- static device scratch (no allocations allowed) ------------
__device__ float g_state[MAXN * MEM];            // merged K/H per node
__device__ float g_stat [MAXN * JPAD];           // per-node static: Ww@w + Wt@tag + bias
__device__ float g_rel  [MAXN * JPAD];           // per-node: Wrel@rel
__device__ float g_leafpre[MAXN * JPAD];         // leaf GRU pre-activations
__device__ float g_WcombT[320 * JPAD];           // [w|tag] static weights, i-major
__device__ float g_leafWT [320 * JPAD];          // leaf_W transposed, i-major
__device__ float g_WrelT  [20  * JPAD];
__device__ float4 g_dyn4[76 * JPAD];             // dyn weights: vi 0..149=U(h), 152..301=Wk(k)
__device__ float g_bias[JPAD];
__device__ float g_c0[JPAD];                     // leaf: leaf_U@leaf_h + leaf_b
__device__ int   g_edge_done[MAXE];
__device__ int   g_child_ready[MAXN];
__device__ int   g_ticket;

// ---------------- asm helpers ----------------
__device__ __forceinline__ int ld_acq(const int* p) {
    int v;
    asm volatile("ld.acquire.gpu.global.b32 %0, [%1];" : "=r"(v) : "l"(p) : "memory");
    return v;
}
__device__ __forceinline__ void st_rel(int* p, int v) {
    asm volatile("st.release.gpu.global.b32 [%0], %1;" :: "l"(p), "r"(v) : "memory");
}
__device__ __forceinline__ float sigf(float x) { return 1.f / (1.f + expf(-x)); }
__device__ __forceinline__ uint32_t smem_u32(const void* p) {
    return (uint32_t)__cvta_generic_to_shared(p);
}
__device__ __forceinline__ uint32_t cluster_rank() {
    uint32_t r; asm("mov.u32 %0, %%cluster_ctarank;" : "=r"(r)); return r;
}
__device__ __forceinline__ uint32_t mapa_rank(uint32_t addr, uint32_t rank) {
    uint32_t r;
    asm("mapa.shared::cluster.u32 %0, %1, %2;" : "=r"(r) : "r"(addr), "r"(rank));
    return r;
}
__device__ __forceinline__ void st_remote_b32(uint32_t remAddr, uint32_t v) {
    asm volatile("st.shared::cluster.b32 [%0], %1;" :: "r"(remAddr), "r"(v) : "memory");
}
__device__ __forceinline__ void cluster_sync2() {
    asm volatile("barrier.cluster.arrive.aligned;" ::: "memory");
    asm volatile("barrier.cluster.wait.aligned;" ::: "memory");
}
__device__ __forceinline__ void poll(const int* f) {
    int n = 0;
    while (!ld_acq(f)) { if (++n > 16) __nanosleep(64); }
}

// column -> (gru row | att row) mapping
__device__ __forceinline__ void colmap(int j, int& row, int& q) {
    row = -1; q = -1;
    if (j < 480) { int m = j % 160; if (m < 150) row = (j / 160) * 150 + m; }
    else if (j < 500) q = j - 480;
}

// ---------------- init ----------------
__global__ void k_init(int N, int E) {
    int stride = gridDim.x * blockDim.x;
    int t0 = blockIdx.x * blockDim.x + threadIdx.x;
    for (int i = t0; i < N * MEM; i += stride) g_state[i] = 0.f;
    for (int i = t0; i < E; i += stride) g_edge_done[i] = 0;
    for (int i = t0; i < N; i += stride) g_child_ready[i] = 0;
    if (t0 == 0) g_ticket = 0;
}

// ---------------- weight reshuffles ----------------
// node_W: (450,490), x layout: [word 0..299 | K 300..449 | rel 450..469 | tag 470..489]
__global__ void k_build_big(const float* __restrict__ node_W, const float* __restrict__ node_U,
                            const float* __restrict__ at_Wb,  const float* __restrict__ leaf_W) {
    int idx = blockIdx.x * blockDim.x + threadIdx.x;
    if (idx >= 320 * JPAD) return;
    int i = idx / JPAD, j = idx % JPAD;
    int row, q; colmap(j, row, q);
    float v = 0.f;
    if (row >= 0)      v = (i < 300) ? node_W[row * 490 + i] : node_W[row * 490 + 470 + (i - 300)];
    else if (q >= 0)   v = (i < 300) ? at_Wb[q * 490 + i]    : at_Wb[q * 490 + 470 + (i - 300)];
    g_WcombT[idx] = v;
    g_leafWT[idx] = (row >= 0) ? leaf_W[row * 320 + i] : 0.f;
    if (i < 304) {
        float mv = 0.f;
        if (i < 150) {
            if (row >= 0) mv = node_U[row * 150 + i];
        } else if (i >= 152 && i < 302) {
            int kk = i - 152;
            if (row >= 0)      mv = node_W[row * 490 + 300 + kk];
            else if (q >= 0)   mv = at_Wb[q * 490 + 300 + kk];
        }
        reinterpret_cast<float*>(g_dyn4)[((i >> 2) * JPAD + j) * 4 + (i & 3)] = mv;
    }
}

__global__ void k_build_small(const float* __restrict__ node_W, const float* __restrict__ at_Wb,
                              const float* __restrict__ node_b, const float* __restrict__ at_bb) {
    int idx = blockIdx.x * blockDim.x + threadIdx.x;
    if (idx < 20 * JPAD) {
        int i = idx / JPAD, j = idx % JPAD;
        int row, q; colmap(j, row, q);
        float v = 0.f;
        if (row >= 0)    v = node_W[row * 490 + 450 + i];
        else if (q >= 0) v = at_Wb[q * 490 + 450 + i];
        g_WrelT[idx] = v;
    } else if (idx < 21 * JPAD) {
        int j = idx - 20 * JPAD;
        int row, q; colmap(j, row, q);
        g_bias[j] = (row >= 0) ? node_b[row] : ((q >= 0) ? at_bb[q] : 0.f);
    }
}

__global__ void k_c0(const float* __restrict__ leaf_U, const float* __restrict__ leaf_h,
                     const float* __restrict__ leaf_b) {
    int j = threadIdx.x;
    if (j >= JPAD) return;
    int row, q; colmap(j, row, q);
    float v = 0.f;
    if (row >= 0) {
        v = leaf_b[row];
        for (int n = 0; n < MEM; n++) v += leaf_U[row * 150 + n] * leaf_h[n];
    }
    g_c0[j] = v;
}

// ---------------- tiled GEMM over [w|tag] (K=320) ----------------
#define BM 64
#define BN 64
#define BK 16
__global__ void __launch_bounds__(256) k_gemm(int mode, int M,
                                              const float* __restrict__ w_emb,
                                              const float* __restrict__ tag_emb,
                                              const int* __restrict__ lids) {
    __shared__ float As[BK][BM + 4];
    __shared__ float Bs[BK][BN];
    const float* B = (mode == 0) ? g_WcombT : g_leafWT;
    int tid = threadIdx.x;
    int tx = tid & 15, ty = tid >> 4;
    int m0 = blockIdx.x * BM, j0 = blockIdx.y * BN;
    int ka = tid & 15, ma = tid >> 4;
    int jb = tid & 63, kb = tid >> 6;
    float acc[4][4] = {};
    for (int k0 = 0; k0 < 320; k0 += BK) {
        #pragma unroll
        for (int it = 0; it < 4; it++) {
            int r = m0 + ma + 16 * it;
            if (r >= M) r = M - 1;
            int row = (mode == 1) ? lids[r] : r;
            int i = k0 + ka;
            As[ka][ma + 16 * it] = (i < 300) ? w_emb[row * 300 + i]
                                             : tag_emb[row * 20 + (i - 300)];
        }
        #pragma unroll
        for (int it = 0; it < 4; it++)
            Bs[kb + 4 * it][jb] = B[(k0 + kb + 4 * it) * JPAD + (j0 + jb)];
        __syncthreads();
        #pragma unroll
        for (int k = 0; k < BK; k++) {
            float4 a4 = *(const float4*)&As[k][ty * 4];
            float4 b4 = *(const float4*)&Bs[k][tx * 4];
            float av[4] = {a4.x, a4.y, a4.z, a4.w};
            float bv[4] = {b4.x, b4.y, b4.z, b4.w};
            #pragma unroll
            for (int mm = 0; mm < 4; mm++)
                #pragma unroll
                for (int jj = 0; jj < 4; jj++)
                    acc[mm][jj] = fmaf(av[mm], bv[jj], acc[mm][jj]);
        }
        __syncthreads();
    }
    #pragma unroll
    for (int mm = 0; mm < 4; mm++) {
        int r = m0 + ty * 4 + mm;
        if (r >= M) continue;
        #pragma unroll
        for (int jj = 0; jj < 4; jj++) {
            int j = j0 + tx * 4 + jj;
            if (mode == 0) g_stat[r * JPAD + j]    = acc[mm][jj] + g_bias[j];
            else           g_leafpre[r * JPAD + j] = acc[mm][jj] + g_c0[j];
        }
    }
}

// ---------------- rel projection (K=20) ----------------
__global__ void __launch_bounds__(512) k_relpart(const float* __restrict__ rel_emb) {
    int n = blockIdx.x, j = threadIdx.x;
    float acc = 0.f;
    #pragma unroll
    for (int q = 0; q < 20; q++)
        acc = fmaf(g_WrelT[q * JPAD + j], __ldg(&rel_emb[n * 20 + q]), acc);
    g_rel[n * JPAD + j] = acc;
}

// ---------------- leaf epilogue ----------------
__global__ void k_leafcomb(const int* __restrict__ lids, const float* __restrict__ leaf_h, int L) {
    int idx = blockIdx.x * blockDim.x + threadIdx.x;
    if (idx >= L * MEM) return;
    int l = idx / MEM, m = idx % MEM;
    float z  = sigf (g_leafpre[l * JPAD + m]);
    float r  = sigf (g_leafpre[l * JPAD + 160 + m]);
    float ht = tanhf(g_leafpre[l * JPAD + 320 + m]);
    g_state[lids[l] * MEM + m] = r * leaf_h[m] + (1.f - z) * ht;
}

__global__ void k_leafready(const int* __restrict__ lids, int L) {
    int l = blockIdx.x * blockDim.x + threadIdx.x;
    if (l < L) g_child_ready[lids[l]] = 1;
}

// ---------------- persistent cluster-4 edge kernel ----------------
// roles 0/1/2: z/r/ht gate CTAs (160 cols, fp32 weights in SMEM)
// role 3:      attention (32 cols, k-only) + combiner + ticket master
__global__ void __launch_bounds__(160, 1) __cluster_dims__(4, 1, 1)
k_edges(const int* __restrict__ ed, int E,
        const float* __restrict__ at_Wa, const float* __restrict__ at_ba) {
    extern __shared__ char smem[];
    volatile int*   tick_sh = (volatile int*)(smem + OFF_TICK);
    volatile float* sa_sh   = (volatile float*)(smem + OFF_SA);
    float*  gatebuf = (float*)(smem + OFF_GATE);
    float*  vsm  = (float*)(smem + OFF_VSM);
    float4* vsm4 = (float4*)vsm;
    float4* sw4  = (float4*)(smem + OFF_W);
    uint32_t base = smem_u32(smem);

    int tid = threadIdx.x;
    int role = (int)cluster_rank();

    // persistent weight slice into SMEM (once per launch)
    if (role < 3) {
        int j0 = role * 160;
        for (int r = 0; r < 76; r++)
            sw4[r * 160 + tid] = g_dyn4[r * JPAD + j0 + tid];
    } else if (tid < 32) {
        for (int r = 38; r < 76; r++)
            sw4[(r - 38) * 32 + tid] = g_dyn4[r * JPAD + 480 + tid];
    }
    if (tid < 4) vsm[150 + (tid >> 1) * 152 + (tid & 1)] = 0.f;  // zero pads 150,151,302,303
    __syncthreads();
    cluster_sync2();                               // everyone alive + weights loaded

    float ba = 0.f, wa = 0.f;
    uint32_t rem_tick0 = 0, rem_tick1 = 0, rem_tick2 = 0, rem_tick3 = 0, rem_gate = 0;
    if (role == 3) {
        ba = *at_ba;
        wa = (tid < 20) ? at_Wa[tid] : 0.f;
        if (tid == 0) {
            rem_tick0 = mapa_rank(base + OFF_TICK, 0);
            rem_tick1 = mapa_rank(base + OFF_TICK, 1);
            rem_tick2 = mapa_rank(base + OFF_TICK, 2);
            rem_tick3 = mapa_rank(base + OFF_TICK, 3);
            int e0 = atomicAdd(&g_ticket, 1);      // bootstrap ticket -> slot 0
            st_remote_b32(rem_tick0, (uint32_t)e0);
            st_remote_b32(rem_tick1, (uint32_t)e0);
            st_remote_b32(rem_tick2, (uint32_t)e0);
            st_remote_b32(rem_tick3, (uint32_t)e0);
        }
    } else {
        int j0 = role * 160;
        rem_gate = mapa_rank(base + OFF_GATE, 3) + (uint32_t)(j0 + tid) * 4u;
    }

    int it = 0;
    while (true) {
        cluster_sync2();                           // sync1: ticket slot it&1 visible
        int e = tick_sh[it & 1];
        if (e >= E) break;
        if (role == 3 && tid == 0) {               // prefetch next ticket -> other slot
            int en = atomicAdd(&g_ticket, 1);
            uint32_t off = 4u * (uint32_t)((it + 1) & 1);
            st_remote_b32(rem_tick0 + off, (uint32_t)en);
            st_remote_b32(rem_tick1 + off, (uint32_t)en);
            st_remote_b32(rem_tick2 + off, (uint32_t)en);
            st_remote_b32(rem_tick3 + off, (uint32_t)en);
        }

        int p = ed[2 * e], c = ed[2 * e + 1];
        bool sib = (e > 0) && (ed[2 * e - 2] == p);

        // prefetch static terms (independent of state)
        float statv = 0.f, relv = 0.f;
        if (role < 3) {
            int j = role * 160 + tid;
            statv = __ldcg(&g_stat[(size_t)p * JPAD + j]);
            relv  = __ldcg(&g_rel [(size_t)c * JPAD + j]);
        } else if (tid < 32) {
            statv = __ldcg(&g_stat[(size_t)p * JPAD + 480 + tid]);
            relv  = __ldcg(&g_rel [(size_t)c * JPAD + 480 + tid]);
        }
        float acc = statv + relv;

        // --- k phase: wait child, load k, k-half matvec ---
        poll(&g_child_ready[c]);                   // every thread polls (acquire)
        if (tid < 150) vsm[152 + tid] = __ldcg(&g_state[c * MEM + tid]);
        __syncthreads();

        if (role < 3) {
            const float4* wp = sw4 + tid;
            #pragma unroll 4
            for (int r = 38; r < 76; r++) {
                float4 w = wp[r * 160]; float4 v = vsm4[r];
                acc += w.x * v.x + w.y * v.y + w.z * v.z + w.w * v.w;
            }
        } else if (tid < 32) {
            const float4* wp = sw4 + tid;
            #pragma unroll 4
            for (int r = 38; r < 76; r++) {
                float4 w = wp[(r - 38) * 32]; float4 v = vsm4[r];
                acc += w.x * v.x + w.y * v.y + w.z * v.z + w.w * v.w;
            }
            // attention depends only on k/static -> finish before sibling wait
            float av = (tid < 20) ? wa * tanhf(acc) : 0.f;
            #pragma unroll
            for (int o = 16; o; o >>= 1) av += __shfl_down_sync(0xffffffffu, av, o);
            if (tid == 0) *sa_sh = sigf(av + ba);
        }

        // --- h phase: wait sibling, load h ---
        if (sib) poll(&g_edge_done[e - 1]);
        if (tid < 150) vsm[tid] = __ldcg(&g_state[p * MEM + tid]);

        if (role < 3) {
            __syncthreads();
            const float4* wp = sw4 + tid;
            #pragma unroll 4
            for (int r = 0; r < 38; r++) {
                float4 w = wp[r * 160]; float4 v = vsm4[r];
                acc += w.x * v.x + w.y * v.y + w.z * v.z + w.w * v.w;
            }
            if (tid < 150) {
                float gv = (role == 2) ? tanhf(acc) : sigf(acc);
                st_remote_b32(rem_gate, __float_as_uint(gv));
            }
            cluster_sync2();                       // sync2: gates delivered
        } else {
            cluster_sync2();                       // sync2 (also CTA barrier for sa_sh/vsm)
            if (tid < 150) {
                float h  = vsm[tid];
                float z  = gatebuf[tid];
                float r_ = gatebuf[160 + tid];
                float ht = gatebuf[320 + tid];
                float a  = *sa_sh;
                float m  = r_ * h + (1.f - z) * ht;
                g_state[p * MEM + tid] = a * m + (1.f - a) * h;
            }
            __threadfence();
            __syncthreads();
            if (tid == 0) {
                st_rel(&g_edge_done[e], 1);
                bool last = (e == E - 1) || (ed[2 * e + 2] != p);
                if (last) st_rel(&g_child_ready[p], 1);
            }
        }
        it++;
    }
    cluster_sync2();
}

__global__ void k_out(float* __restrict__ out) {
    int m = threadIdx.x;
    if (m < MEM) out[m] = g_state[m];
}

// ---------------- launch ----------------
extern "C" void kernel_launch(void* const* d_in, const int* in_sizes, int n_in,
                              void* d_out, int out_size) {
    const float* w_emb   = (const float*)d_in[0];
    const float* tag_emb = (const float*)d_in[1];
    const float* rel_emb = (const float*)d_in[2];
    const float* leaf_h  = (const float*)d_in[3];
    const float* leaf_W  = (const float*)d_in[4];
    const float* leaf_U  = (const float*)d_in[5];
    const float* leaf_b  = (const float*)d_in[6];
    const float* node_W  = (const float*)d_in[7];
    const float* node_U  = (const float*)d_in[8];
    const float* node_b  = (const float*)d_in[9];
    const float* at_Wb   = (const float*)d_in[10];
    const float* at_bb   = (const float*)d_in[11];
    const float* at_Wa   = (const float*)d_in[12];
    const float* at_ba   = (const float*)d_in[13];
    const int*   edges   = (const int*)d_in[14];
    const int*   lids    = (const int*)d_in[15];

    int N = in_sizes[0] / 300;
    int E = in_sizes[14] / 2;
    int L = in_sizes[15];

    cudaFuncSetAttribute(k_edges, cudaFuncAttributeMaxDynamicSharedMemorySize, EDGE_SMEM);

    k_init<<<256, 256>>>(N, E);
    k_build_big<<<(320 * JPAD + 255) / 256, 256>>>(node_W, node_U, at_Wb, leaf_W);
    k_build_small<<<(21 * JPAD + 255) / 256, 256>>>(node_W, at_Wb, node_b, at_bb);
    k_c0<<<1, 512>>>(leaf_U, leaf_h, leaf_b);
    k_gemm<<<dim3((N + BM - 1) / BM, JPAD / BN), 256>>>(0, N, w_emb, tag_emb, lids);
    k_gemm<<<dim3((L + BM - 1) / BM, JPAD / BN), 256>>>(1, L, w_emb, tag_emb, lids);
    k_relpart<<<N, 512>>>(rel_emb);
    k_leafcomb<<<(L * MEM + 255) / 256, 256>>>(lids, leaf_h, L);
    k_leafready<<<(L + 255) / 256, 256>>>(lids, L);
    k_edges<<<4 * NCLUST, 160, EDGE_SMEM>>>(edges, E, at_Wa, at_ba);
    k_out<<<1, 256>>>((float*)d_out);
}

// round 9
// speedup vs baseline: 1.8127x; 1.5183x over previous
#include <cuda_runtime.h>
#include <cuda_bf16.h>
#include <cstdint>

#define MAXN 32768
#define MAXE 32768
#define MEM  150
#define JPAD 512
#define NCLUST 33

// ---- shared-memory byte offsets (same layout in every CTA) ----
#define OFF_TICK 0                  // 2 ints (double-buffered run ticket)
#define OFF_SA   8                  // 2 floats (double-buffered attention scalar)
#define OFF_SVAL 16                 // int (child-ready value)
#define OFF_GATE 32                 // 2 slots * 480 floats -> [32, 3872)
#define OFF_VSM  3872               // 304 floats (h 0..151 | k 152..303), 16B aligned
#define OFF_W    5088               // 76*160 float4 = 194560B
#define EDGE_SMEM (OFF_W + 76*160*16)

// ---------------- static device scratch (no allocations allowed) ------------
__device__ float g_state[MAXN * MEM];            // node K (written once per node)
__device__ float g_stat [MAXN * JPAD];           // per-node static: Ww@w + Wt@tag + bias
__device__ float g_rel  [MAXN * JPAD];           // per-node: Wrel@rel
__device__ float g_leafpre[MAXN * JPAD];         // leaf GRU pre-activations
__device__ float g_kpre [MAXN * JPAD];           // leaf nodes: Wk@K[leaf] precomputed
__device__ float g_WcombT[320 * JPAD];           // [w|tag] static weights, i-major
__device__ float g_leafWT [320 * JPAD];          // leaf_W transposed, i-major
__device__ float g_WkT   [160 * JPAD];           // k-part weights, i-major (for kpre GEMM)
__device__ float g_WrelT  [20  * JPAD];
__device__ float4 g_dyn4[76 * JPAD];             // dyn weights: vi 0..149=U(h), 152..301=Wk(k)
__device__ float g_bias[JPAD];
__device__ float g_c0[JPAD];                     // leaf: leaf_U@leaf_h + leaf_b
__device__ int   g_child_ready[MAXN];            // 0=not ready, 1=internal done, 2=leaf
__device__ int   g_run_start[MAXE + 1];
__device__ int   g_run_parent[MAXE];
__device__ int   g_R;
__device__ int   g_ticket;

// ---------------- asm helpers ----------------
__device__ __forceinline__ int ld_acq(const int* p) {
    int v;
    asm volatile("ld.acquire.gpu.global.b32 %0, [%1];" : "=r"(v) : "l"(p) : "memory");
    return v;
}
__device__ __forceinline__ void st_rel(int* p, int v) {
    asm volatile("st.release.gpu.global.b32 [%0], %1;" :: "l"(p), "r"(v) : "memory");
}
__device__ __forceinline__ float sigf(float x) { return 1.f / (1.f + expf(-x)); }
__device__ __forceinline__ uint32_t smem_u32(const void* p) {
    return (uint32_t)__cvta_generic_to_shared(p);
}
__device__ __forceinline__ uint32_t cluster_rank() {
    uint32_t r; asm("mov.u32 %0, %%cluster_ctarank;" : "=r"(r)); return r;
}
__device__ __forceinline__ uint32_t mapa_rank(uint32_t addr, uint32_t rank) {
    uint32_t r;
    asm("mapa.shared::cluster.u32 %0, %1, %2;" : "=r"(r) : "r"(addr), "r"(rank));
    return r;
}
__device__ __forceinline__ void st_remote_b32(uint32_t remAddr, uint32_t v) {
    asm volatile("st.shared::cluster.b32 [%0], %1;" :: "r"(remAddr), "r"(v) : "memory");
}
__device__ __forceinline__ void cluster_sync2() {
    asm volatile("barrier.cluster.arrive.aligned;" ::: "memory");
    asm volatile("barrier.cluster.wait.aligned;" ::: "memory");
}

// column -> (gru row | att row) mapping
__device__ __forceinline__ void colmap(int j, int& row, int& q) {
    row = -1; q = -1;
    if (j < 480) { int m = j % 160; if (m < 150) row = (j / 160) * 150 + m; }
    else if (j < 500) q = j - 480;
}

// ---------------- init ----------------
__global__ void k_init(int N, int E) {
    int stride = gridDim.x * blockDim.x;
    int t0 = blockIdx.x * blockDim.x + threadIdx.x;
    for (int i = t0; i < N; i += stride) g_child_ready[i] = 0;
    if (t0 == 0) g_ticket = 0;
}

// ---------------- run table (single block scan) ----------------
__global__ void k_runscan(const int* __restrict__ ed, int E) {
    __shared__ int sflag[1024];
    __shared__ int sbase;
    int tid = threadIdx.x;
    if (tid == 0) sbase = 0;
    __syncthreads();
    for (int chunk = 0; chunk < E; chunk += 1024) {
        int i = chunk + tid;
        int f = 0;
        if (i < E) f = (i == 0) || (ed[2 * i] != ed[2 * i - 2]);
        sflag[tid] = f;
        __syncthreads();
        for (int off = 1; off < 1024; off <<= 1) {
            int v = (tid >= off) ? sflag[tid - off] : 0;
            __syncthreads();
            sflag[tid] += v;
            __syncthreads();
        }
        if (i < E && f) {
            int rid = sbase + sflag[tid] - 1;
            g_run_start[rid] = i;
            g_run_parent[rid] = ed[2 * i];
        }
        __syncthreads();
        if (tid == 0) sbase += sflag[1023];
        __syncthreads();
    }
    if (tid == 0) { g_R = sbase; g_run_start[sbase] = E; }
}

// ---------------- weight reshuffles ----------------
// node_W: (450,490), x layout: [word 0..299 | K 300..449 | rel 450..469 | tag 470..489]
__global__ void k_build_big(const float* __restrict__ node_W, const float* __restrict__ node_U,
                            const float* __restrict__ at_Wb,  const float* __restrict__ leaf_W) {
    int idx = blockIdx.x * blockDim.x + threadIdx.x;
    if (idx >= 320 * JPAD) return;
    int i = idx / JPAD, j = idx % JPAD;
    int row, q; colmap(j, row, q);
    float v = 0.f;
    if (row >= 0)      v = (i < 300) ? node_W[row * 490 + i] : node_W[row * 490 + 470 + (i - 300)];
    else if (q >= 0)   v = (i < 300) ? at_Wb[q * 490 + i]    : at_Wb[q * 490 + 470 + (i - 300)];
    g_WcombT[idx] = v;
    g_leafWT[idx] = (row >= 0) ? leaf_W[row * 320 + i] : 0.f;
    if (i < 304) {
        float mv = 0.f;
        if (i < 150) {
            if (row >= 0) mv = node_U[row * 150 + i];
        } else if (i >= 152 && i < 302) {
            int kk = i - 152;
            if (row >= 0)      mv = node_W[row * 490 + 300 + kk];
            else if (q >= 0)   mv = at_Wb[q * 490 + 300 + kk];
        }
        reinterpret_cast<float*>(g_dyn4)[((i >> 2) * JPAD + j) * 4 + (i & 3)] = mv;
    }
    if (i < 160) {
        float kv = 0.f;
        if (i < 150) {
            if (row >= 0)      kv = node_W[row * 490 + 300 + i];
            else if (q >= 0)   kv = at_Wb[q * 490 + 300 + i];
        }
        g_WkT[i * JPAD + j] = kv;
    }
}

__global__ void k_build_small(const float* __restrict__ node_W, const float* __restrict__ at_Wb,
                              const float* __restrict__ node_b, const float* __restrict__ at_bb) {
    int idx = blockIdx.x * blockDim.x + threadIdx.x;
    if (idx < 20 * JPAD) {
        int i = idx / JPAD, j = idx % JPAD;
        int row, q; colmap(j, row, q);
        float v = 0.f;
        if (row >= 0)    v = node_W[row * 490 + 450 + i];
        else if (q >= 0) v = at_Wb[q * 490 + 450 + i];
        g_WrelT[idx] = v;
    } else if (idx < 21 * JPAD) {
        int j = idx - 20 * JPAD;
        int row, q; colmap(j, row, q);
        g_bias[j] = (row >= 0) ? node_b[row] : ((q >= 0) ? at_bb[q] : 0.f);
    }
}

__global__ void k_c0(const float* __restrict__ leaf_U, const float* __restrict__ leaf_h,
                     const float* __restrict__ leaf_b) {
    int j = threadIdx.x;
    if (j >= JPAD) return;
    int row, q; colmap(j, row, q);
    float v = 0.f;
    if (row >= 0) {
        v = leaf_b[row];
        for (int n = 0; n < MEM; n++) v += leaf_U[row * 150 + n] * leaf_h[n];
    }
    g_c0[j] = v;
}

// ---------------- tiled GEMM ----------------
// mode 0: g_stat[n][j]    = [w|tag][n] @ WcombT + bias   (M=N, K=320)
// mode 1: g_leafpre[l][j] = [w|tag][lids[l]] @ leafWT + c0 (M=L, K=320)
// mode 2: g_kpre[lids[l]][j] = K_leaf[l] @ WkT           (M=L, K=160)
#define BM 64
#define BN 64
#define BK 16
__global__ void __launch_bounds__(256) k_gemm(int mode, int M, int Ktot,
                                              const float* __restrict__ w_emb,
                                              const float* __restrict__ tag_emb,
                                              const int* __restrict__ lids) {
    __shared__ float As[BK][BM + 4];
    __shared__ float Bs[BK][BN];
    const float* B = (mode == 0) ? g_WcombT : ((mode == 1) ? g_leafWT : g_WkT);
    int tid = threadIdx.x;
    int tx = tid & 15, ty = tid >> 4;
    int m0 = blockIdx.x * BM, j0 = blockIdx.y * BN;
    int ka = tid & 15, ma = tid >> 4;
    int jb = tid & 63, kb = tid >> 6;
    float acc[4][4] = {};
    for (int k0 = 0; k0 < Ktot; k0 += BK) {
        #pragma unroll
        for (int it = 0; it < 4; it++) {
            int r = m0 + ma + 16 * it;
            if (r >= M) r = M - 1;
            int row = (mode >= 1) ? lids[r] : r;
            int i = k0 + ka;
            float av;
            if (mode == 2) av = (i < 150) ? g_state[row * MEM + i] : 0.f;
            else av = (i < 300) ? w_emb[row * 300 + i] : tag_emb[row * 20 + (i - 300)];
            As[ka][ma + 16 * it] = av;
        }
        #pragma unroll
        for (int it = 0; it < 4; it++)
            Bs[kb + 4 * it][jb] = B[(k0 + kb + 4 * it) * JPAD + (j0 + jb)];
        __syncthreads();
        #pragma unroll
        for (int k = 0; k < BK; k++) {
            float4 a4 = *(const float4*)&As[k][ty * 4];
            float4 b4 = *(const float4*)&Bs[k][tx * 4];
            float av[4] = {a4.x, a4.y, a4.z, a4.w};
            float bv[4] = {b4.x, b4.y, b4.z, b4.w};
            #pragma unroll
            for (int mm = 0; mm < 4; mm++)
                #pragma unroll
                for (int jj = 0; jj < 4; jj++)
                    acc[mm][jj] = fmaf(av[mm], bv[jj], acc[mm][jj]);
        }
        __syncthreads();
    }
    #pragma unroll
    for (int mm = 0; mm < 4; mm++) {
        int r = m0 + ty * 4 + mm;
        if (r >= M) continue;
        #pragma unroll
        for (int jj = 0; jj < 4; jj++) {
            int j = j0 + tx * 4 + jj;
            if (mode == 0)      g_stat[r * JPAD + j]    = acc[mm][jj] + g_bias[j];
            else if (mode == 1) g_leafpre[r * JPAD + j] = acc[mm][jj] + g_c0[j];
            else                g_kpre[(size_t)lids[r] * JPAD + j] = acc[mm][jj];
        }
    }
}

// ---------------- rel projection (K=20) ----------------
__global__ void __launch_bounds__(512) k_relpart(const float* __restrict__ rel_emb) {
    int n = blockIdx.x, j = threadIdx.x;
    float acc = 0.f;
    #pragma unroll
    for (int q = 0; q < 20; q++)
        acc = fmaf(g_WrelT[q * JPAD + j], __ldg(&rel_emb[n * 20 + q]), acc);
    g_rel[n * JPAD + j] = acc;
}

// ---------------- leaf epilogue ----------------
__global__ void k_leafcomb(const int* __restrict__ lids, const float* __restrict__ leaf_h, int L) {
    int idx = blockIdx.x * blockDim.x + threadIdx.x;
    if (idx >= L * MEM) return;
    int l = idx / MEM, m = idx % MEM;
    float z  = sigf (g_leafpre[l * JPAD + m]);
    float r  = sigf (g_leafpre[l * JPAD + 160 + m]);
    float ht = tanhf(g_leafpre[l * JPAD + 320 + m]);
    g_state[lids[l] * MEM + m] = r * leaf_h[m] + (1.f - z) * ht;
}

__global__ void k_leafready(const int* __restrict__ lids, int L) {
    int l = blockIdx.x * blockDim.x + threadIdx.x;
    if (l < L) g_child_ready[lids[l]] = 2;         // 2 = leaf (kpre valid)
}

// ---------------- persistent cluster-4 run-based edge kernel ----------------
// roles 0/1/2: z/r/ht gate CTAs (160 cols); role 3: attention (32 cols)
// Gates + attention scalar broadcast to ALL CTAs; every CTA combines locally.
__global__ void __launch_bounds__(160, 1) __cluster_dims__(4, 1, 1)
k_edges(const int* __restrict__ ed,
        const float* __restrict__ at_Wa, const float* __restrict__ at_ba) {
    extern __shared__ char smem[];
    volatile int*   tick_sh = (volatile int*)(smem + OFF_TICK);
    volatile float* sa_sh   = (volatile float*)(smem + OFF_SA);
    volatile int*   sval_sh = (volatile int*)(smem + OFF_SVAL);
    float*  gatebuf = (float*)(smem + OFF_GATE);   // [2][480]
    float*  vsm  = (float*)(smem + OFF_VSM);
    float4* vsm4 = (float4*)vsm;
    float4* sw4  = (float4*)(smem + OFF_W);
    uint32_t base = smem_u32(smem);

    int tid = threadIdx.x;
    int role = (int)cluster_rank();

    // persistent weight slice into SMEM
    if (role < 3) {
        int j0 = role * 160;
        for (int r = 0; r < 76; r++)
            sw4[r * 160 + tid] = g_dyn4[r * JPAD + j0 + tid];
    } else if (tid < 32) {
        for (int r = 38; r < 76; r++)
            sw4[(r - 38) * 32 + tid] = g_dyn4[r * JPAD + 480 + tid];
    }
    if (tid < 4) vsm[150 + (tid >> 1) * 152 + (tid & 1)] = 0.f;  // pads 150,151,302,303
    __syncthreads();

    // broadcast-address setup
    float ba = 0.f, wa = 0.f;
    uint32_t remG0 = 0, remG1 = 0, remG2 = 0, remG3 = 0;   // gate dests (workers)
    uint32_t remS0 = 0, remS1 = 0, remS2 = 0;              // sa dests (role3 t0)
    uint32_t remT0 = 0, remT1 = 0, remT2 = 0, remT3 = 0;   // ticket dests (role0 t0)
    if (role < 3) {
        uint32_t off = (uint32_t)(OFF_GATE) + (uint32_t)(role * 160 + tid) * 4u;
        remG0 = mapa_rank(base + off, 0);
        remG1 = mapa_rank(base + off, 1);
        remG2 = mapa_rank(base + off, 2);
        remG3 = mapa_rank(base + off, 3);
    } else {
        ba = *at_ba;
        wa = (tid < 20) ? at_Wa[tid] : 0.f;
        if (tid == 0) {
            remS0 = mapa_rank(base + OFF_SA, 0);
            remS1 = mapa_rank(base + OFF_SA, 1);
            remS2 = mapa_rank(base + OFF_SA, 2);
        }
    }
    if (role == 0 && tid == 0) {
        remT0 = mapa_rank(base + OFF_TICK, 0);
        remT1 = mapa_rank(base + OFF_TICK, 1);
        remT2 = mapa_rank(base + OFF_TICK, 2);
        remT3 = mapa_rank(base + OFF_TICK, 3);
        int e0 = atomicAdd(&g_ticket, 1);          // bootstrap -> slot 0
        st_remote_b32(remT0, (uint32_t)e0);
        st_remote_b32(remT1, (uint32_t)e0);
        st_remote_b32(remT2, (uint32_t)e0);
        st_remote_b32(remT3, (uint32_t)e0);
    }
    cluster_sync2();

    int R = g_R;
    int runpar = 0, epar = 0;

    while (true) {
        int r = tick_sh[runpar];
        if (r >= R) break;
        if (role == 0 && tid == 0) {               // prefetch next run ticket
            int rn = atomicAdd(&g_ticket, 1);
            uint32_t off = 4u * (uint32_t)(runpar ^ 1);
            st_remote_b32(remT0 + off, (uint32_t)rn);
            st_remote_b32(remT1 + off, (uint32_t)rn);
            st_remote_b32(remT2 + off, (uint32_t)rn);
            st_remote_b32(remT3 + off, (uint32_t)rn);
        }
        int es = g_run_start[r], ee = g_run_start[r + 1];
        int p  = g_run_parent[r];

        float statv = 0.f;
        if (role < 3)       statv = __ldcg(&g_stat[(size_t)p * JPAD + role * 160 + tid]);
        else if (tid < 32)  statv = __ldcg(&g_stat[(size_t)p * JPAD + 480 + tid]);

        bool first = true;
        float hreg = 0.f;

        for (int e = es; e < ee; e++) {
            int c = __ldcg(&ed[2 * e + 1]);
            float relv = 0.f;
            if (role < 3)      relv = __ldcg(&g_rel[(size_t)c * JPAD + role * 160 + tid]);
            else if (tid < 32) relv = __ldcg(&g_rel[(size_t)c * JPAD + 480 + tid]);
            float acc = statv + relv;

            // h-half matvec (sibling edges only; overlaps child wait below)
            if (!first && role < 3) {
                const float4* wp = sw4 + tid;
                #pragma unroll 4
                for (int r2 = 0; r2 < 38; r2++) {
                    float4 w = wp[r2 * 160]; float4 v = vsm4[r2];
                    acc += w.x * v.x + w.y * v.y + w.z * v.z + w.w * v.w;
                }
            }

            // child dependency (single-thread poll)
            if (tid == 0) {
                int v, n = 0;
                while (!(v = ld_acq(&g_child_ready[c]))) { if (++n > 16) __nanosleep(64); }
                *sval_sh = v;
            }
            __syncthreads();
            int sv = *sval_sh;

            if (sv == 2) {                         // leaf child: precomputed k-contrib
                if (role < 3)      acc += __ldcg(&g_kpre[(size_t)c * JPAD + role * 160 + tid]);
                else if (tid < 32) acc += __ldcg(&g_kpre[(size_t)c * JPAD + 480 + tid]);
            } else {                               // internal child: k-matvec
                if (tid < 150) vsm[152 + tid] = __ldcg(&g_state[c * MEM + tid]);
                __syncthreads();
                if (role < 3) {
                    const float4* wp = sw4 + tid;
                    #pragma unroll 4
                    for (int r2 = 38; r2 < 76; r2++) {
                        float4 w = wp[r2 * 160]; float4 v = vsm4[r2];
                        acc += w.x * v.x + w.y * v.y + w.z * v.z + w.w * v.w;
                    }
                } else if (tid < 32) {
                    const float4* wp = sw4 + tid;
                    #pragma unroll 4
                    for (int r2 = 38; r2 < 76; r2++) {
                        float4 w = wp[(r2 - 38) * 32]; float4 v = vsm4[r2];
                        acc += w.x * v.x + w.y * v.y + w.z * v.z + w.w * v.w;
                    }
                }
            }

            // broadcast gates / attention scalar to all CTAs
            if (role < 3) {
                if (tid < 150) {
                    float gv = (role == 2) ? tanhf(acc) : sigf(acc);
                    uint32_t u = __float_as_uint(gv);
                    uint32_t soff = (uint32_t)(epar * 480) * 4u;
                    st_remote_b32(remG0 + soff, u);
                    st_remote_b32(remG1 + soff, u);
                    st_remote_b32(remG2 + soff, u);
                    st_remote_b32(remG3 + soff, u);
                }
            } else {
                float av = (tid < 20) ? wa * tanhf(acc) : 0.f;
                if (tid < 32) {
                    #pragma unroll
                    for (int o = 16; o; o >>= 1) av += __shfl_down_sync(0xffffffffu, av, o);
                    if (tid == 0) {
                        float a = sigf(av + ba);
                        uint32_t u = __float_as_uint(a);
                        uint32_t soff = 4u * (uint32_t)epar;
                        sa_sh[epar] = a;
                        st_remote_b32(remS0 + soff, u);
                        st_remote_b32(remS1 + soff, u);
                        st_remote_b32(remS2 + soff, u);
                    }
                }
            }
            cluster_sync2();                       // gates + a delivered everywhere

            // local combine (every CTA keeps its own h copy)
            float a = sa_sh[epar];
            if (tid < 150) {
                const float* gb = gatebuf + epar * 480;
                float z = gb[tid], r_ = gb[160 + tid], ht = gb[320 + tid];
                float h = first ? 0.f : vsm[tid];
                float m = r_ * h + (1.f - z) * ht;
                hreg = a * m + (1.f - a) * h;
                vsm[tid] = hreg;
            }
            __syncthreads();                       // h ready for next edge's h-matvec
            first = false;
            epar ^= 1;
        }

        // run end: publish K[p] = H[p] and release
        if (role == 3) {
            if (tid < 150) g_state[p * MEM + tid] = hreg;
            __threadfence();
            __syncthreads();
            if (tid == 0) st_rel(&g_child_ready[p], 1);
        }
        runpar ^= 1;
    }
    cluster_sync2();
}

__global__ void k_out(float* __restrict__ out) {
    int m = threadIdx.x;
    if (m < MEM) out[m] = g_state[m];
}

// ---------------- launch ----------------
extern "C" void kernel_launch(void* const* d_in, const int* in_sizes, int n_in,
                              void* d_out, int out_size) {
    const float* w_emb   = (const float*)d_in[0];
    const float* tag_emb = (const float*)d_in[1];
    const float* rel_emb = (const float*)d_in[2];
    const float* leaf_h  = (const float*)d_in[3];
    const float* leaf_W  = (const float*)d_in[4];
    const float* leaf_U  = (const float*)d_in[5];
    const float* leaf_b  = (const float*)d_in[6];
    const float* node_W  = (const float*)d_in[7];
    const float* node_U  = (const float*)d_in[8];
    const float* node_b  = (const float*)d_in[9];
    const float* at_Wb   = (const float*)d_in[10];
    const float* at_bb   = (const float*)d_in[11];
    const float* at_Wa   = (const float*)d_in[12];
    const float* at_ba   = (const float*)d_in[13];
    const int*   edges   = (const int*)d_in[14];
    const int*   lids    = (const int*)d_in[15];

    int N = in_sizes[0] / 300;
    int E = in_sizes[14] / 2;
    int L = in_sizes[15];

    cudaFuncSetAttribute(k_edges, cudaFuncAttributeMaxDynamicSharedMemorySize, EDGE_SMEM);

    k_init<<<64, 256>>>(N, E);
    k_runscan<<<1, 1024>>>(edges, E);
    k_build_big<<<(320 * JPAD + 255) / 256, 256>>>(node_W, node_U, at_Wb, leaf_W);
    k_build_small<<<(21 * JPAD + 255) / 256, 256>>>(node_W, at_Wb, node_b, at_bb);
    k_c0<<<1, 512>>>(leaf_U, leaf_h, leaf_b);
    k_gemm<<<dim3((N + BM - 1) / BM, JPAD / BN), 256>>>(0, N, 320, w_emb, tag_emb, lids);
    k_gemm<<<dim3((L + BM - 1) / BM, JPAD / BN), 256>>>(1, L, 320, w_emb, tag_emb, lids);
    k_relpart<<<N, 512>>>(rel_emb);
    k_leafcomb<<<(L * MEM + 255) / 256, 256>>>(lids, leaf_h, L);
    k_gemm<<<dim3((L + BM - 1) / BM, JPAD / BN), 256>>>(2, L, 160, w_emb, tag_emb, lids);
    k_leafready<<<(L + 255) / 256, 256>>>(lids, L);
    k_edges<<<4 * NCLUST, 160, EDGE_SMEM>>>(edges, at_Wa, at_ba);
    k_out<<<1, 256>>>((float*)d_out);
}

// round 10
// speedup vs baseline: 1.9211x; 1.0598x over previous
#include <cuda_runtime.h>
#include <cuda_bf16.h>
#include <cstdint>

#define MAXN 32768
#define MAXE 32768
#define MEM  150
#define JPAD 512
#define NCLUST 33

// ---- shared-memory byte offsets (same layout in every CTA) ----
#define OFF_TICK 0                  // 2 ints (double-buffered path ticket)
#define OFF_SA   8                  // 2 floats (double-buffered attention scalar)
#define OFF_SVAL 16                 // int (child-ready value)
#define OFF_GATE 32                 // 2 slots * 480 floats -> [32, 3872)
#define OFF_VSM  3872               // 304 floats (h 0..151 | k 152..303), 16B aligned
#define OFF_W    5088               // 76*160 float4 = 194560B
#define EDGE_SMEM (OFF_W + 76*160*16)

// ---------------- static device scratch (no allocations allowed) ------------
__device__ float g_state[MAXN * MEM];            // node K (published for chain tops + leaves)
__device__ float g_stat [MAXN * JPAD];           // per-node static: Ww@w + Wt@tag + bias
__device__ float g_rel  [MAXN * JPAD];           // per-node: Wrel@rel
__device__ float g_leafpre[MAXN * JPAD];         // leaf GRU pre-activations
__device__ float g_kpre [MAXN * JPAD];           // leaf nodes: Wk@K[leaf] precomputed
__device__ float g_WcombT[320 * JPAD];           // [w|tag] static weights, i-major
__device__ float g_leafWT [320 * JPAD];          // leaf_W transposed, i-major
__device__ float g_WkT   [160 * JPAD];           // k-part weights, i-major (for kpre GEMM)
__device__ float g_WrelT  [20  * JPAD];
__device__ float4 g_dyn4[76 * JPAD];             // dyn weights: vi 0..149=U(h), 152..301=Wk(k)
__device__ float g_bias[JPAD];
__device__ float g_c0[JPAD];                     // leaf: leaf_U@leaf_h + leaf_b
__device__ int   g_child_ready[MAXN];            // 0=not ready, 1=internal done, 2=leaf
__device__ int   g_run_start[MAXE + 1];
__device__ int   g_run_of[MAXN];                 // node -> run id (-1 = leaf)
__device__ int   g_desig[MAXN];                  // node -> first child (chain link)
__device__ int   g_parent_of[MAXN];              // child -> parent
__device__ int   g_path_top[MAXE];               // chain tops, node index descending
__device__ int   g_P;                            // number of chains
__device__ int   g_R;
__device__ int   g_ticket;

// ---------------- asm helpers ----------------
__device__ __forceinline__ int ld_acq(const int* p) {
    int v;
    asm volatile("ld.acquire.gpu.global.b32 %0, [%1];" : "=r"(v) : "l"(p) : "memory");
    return v;
}
__device__ __forceinline__ void st_rel(int* p, int v) {
    asm volatile("st.release.gpu.global.b32 [%0], %1;" :: "l"(p), "r"(v) : "memory");
}
__device__ __forceinline__ float sigf(float x) { return 1.f / (1.f + expf(-x)); }
__device__ __forceinline__ uint32_t smem_u32(const void* p) {
    return (uint32_t)__cvta_generic_to_shared(p);
}
__device__ __forceinline__ uint32_t cluster_rank() {
    uint32_t r; asm("mov.u32 %0, %%cluster_ctarank;" : "=r"(r)); return r;
}
__device__ __forceinline__ uint32_t mapa_rank(uint32_t addr, uint32_t rank) {
    uint32_t r;
    asm("mapa.shared::cluster.u32 %0, %1, %2;" : "=r"(r) : "r"(addr), "r"(rank));
    return r;
}
__device__ __forceinline__ void st_remote_b32(uint32_t remAddr, uint32_t v) {
    asm volatile("st.shared::cluster.b32 [%0], %1;" :: "r"(remAddr), "r"(v) : "memory");
}
__device__ __forceinline__ void cluster_sync2() {
    asm volatile("barrier.cluster.arrive.aligned;" ::: "memory");
    asm volatile("barrier.cluster.wait.aligned;" ::: "memory");
}

// column -> (gru row | att row) mapping
__device__ __forceinline__ void colmap(int j, int& row, int& q) {
    row = -1; q = -1;
    if (j < 480) { int m = j % 160; if (m < 150) row = (j / 160) * 150 + m; }
    else if (j < 500) q = j - 480;
}

// ---------------- init ----------------
__global__ void k_init(int N, int E) {
    int stride = gridDim.x * blockDim.x;
    int t0 = blockIdx.x * blockDim.x + threadIdx.x;
    for (int i = t0; i < N; i += stride) { g_child_ready[i] = 0; g_run_of[i] = -1; }
    if (t0 == 0) g_ticket = 0;
}

// ---------------- run table (single block scan) ----------------
__global__ void k_runscan(const int* __restrict__ ed, int E) {
    __shared__ int sflag[1024];
    __shared__ int sbase;
    int tid = threadIdx.x;
    if (tid == 0) sbase = 0;
    __syncthreads();
    for (int chunk = 0; chunk < E; chunk += 1024) {
        int i = chunk + tid;
        int f = 0;
        if (i < E) f = (i == 0) || (ed[2 * i] != ed[2 * i - 2]);
        sflag[tid] = f;
        __syncthreads();
        for (int off = 1; off < 1024; off <<= 1) {
            int v = (tid >= off) ? sflag[tid - off] : 0;
            __syncthreads();
            sflag[tid] += v;
            __syncthreads();
        }
        if (i < E && f) {
            int rid = sbase + sflag[tid] - 1;
            int p = ed[2 * i];
            g_run_start[rid] = i;
            g_run_of[p] = rid;
            g_desig[p] = ed[2 * i + 1];            // first child = chain link
        }
        __syncthreads();
        if (tid == 0) sbase += sflag[1023];
        __syncthreads();
    }
    if (tid == 0) { g_R = sbase; g_run_start[sbase] = E; }
}

// ---------------- parent map ----------------
__global__ void k_parent(const int* __restrict__ ed, int E) {
    int i = blockIdx.x * blockDim.x + threadIdx.x;
    if (i < E) g_parent_of[ed[2 * i + 1]] = ed[2 * i];
    if (i == 0) g_parent_of[0] = -1;
}

// ---------------- chain tops, node index descending (single block scan) -----
__global__ void k_pathscan(int N) {
    __shared__ int sflag[1024];
    __shared__ int sbase;
    int tid = threadIdx.x;
    if (tid == 0) sbase = 0;
    __syncthreads();
    for (int chunk = 0; chunk < N; chunk += 1024) {
        int nr = chunk + tid;
        int n = N - 1 - nr;
        int f = 0;
        if (nr < N && g_run_of[n] >= 0) {          // internal node
            if (n == 0) f = 1;
            else f = (g_desig[g_parent_of[n]] != n) ? 1 : 0;   // not chain-linked
        }
        sflag[tid] = f;
        __syncthreads();
        for (int off = 1; off < 1024; off <<= 1) {
            int v = (tid >= off) ? sflag[tid - off] : 0;
            __syncthreads();
            sflag[tid] += v;
            __syncthreads();
        }
        if (f) g_path_top[sbase + sflag[tid] - 1] = n;
        __syncthreads();
        if (tid == 0) sbase += sflag[1023];
        __syncthreads();
    }
    if (tid == 0) g_P = sbase;
}

// ---------------- weight reshuffles ----------------
// node_W: (450,490), x layout: [word 0..299 | K 300..449 | rel 450..469 | tag 470..489]
__global__ void k_build_big(const float* __restrict__ node_W, const float* __restrict__ node_U,
                            const float* __restrict__ at_Wb,  const float* __restrict__ leaf_W) {
    int idx = blockIdx.x * blockDim.x + threadIdx.x;
    if (idx >= 320 * JPAD) return;
    int i = idx / JPAD, j = idx % JPAD;
    int row, q; colmap(j, row, q);
    float v = 0.f;
    if (row >= 0)      v = (i < 300) ? node_W[row * 490 + i] : node_W[row * 490 + 470 + (i - 300)];
    else if (q >= 0)   v = (i < 300) ? at_Wb[q * 490 + i]    : at_Wb[q * 490 + 470 + (i - 300)];
    g_WcombT[idx] = v;
    g_leafWT[idx] = (row >= 0) ? leaf_W[row * 320 + i] : 0.f;
    if (i < 304) {
        float mv = 0.f;
        if (i < 150) {
            if (row >= 0) mv = node_U[row * 150 + i];
        } else if (i >= 152 && i < 302) {
            int kk = i - 152;
            if (row >= 0)      mv = node_W[row * 490 + 300 + kk];
            else if (q >= 0)   mv = at_Wb[q * 490 + 300 + kk];
        }
        reinterpret_cast<float*>(g_dyn4)[((i >> 2) * JPAD + j) * 4 + (i & 3)] = mv;
    }
    if (i < 160) {
        float kv = 0.f;
        if (i < 150) {
            if (row >= 0)      kv = node_W[row * 490 + 300 + i];
            else if (q >= 0)   kv = at_Wb[q * 490 + 300 + i];
        }
        g_WkT[i * JPAD + j] = kv;
    }
}

__global__ void k_build_small(const float* __restrict__ node_W, const float* __restrict__ at_Wb,
                              const float* __restrict__ node_b, const float* __restrict__ at_bb) {
    int idx = blockIdx.x * blockDim.x + threadIdx.x;
    if (idx < 20 * JPAD) {
        int i = idx / JPAD, j = idx % JPAD;
        int row, q; colmap(j, row, q);
        float v = 0.f;
        if (row >= 0)    v = node_W[row * 490 + 450 + i];
        else if (q >= 0) v = at_Wb[q * 490 + 450 + i];
        g_WrelT[idx] = v;
    } else if (idx < 21 * JPAD) {
        int j = idx - 20 * JPAD;
        int row, q; colmap(j, row, q);
        g_bias[j] = (row >= 0) ? node_b[row] : ((q >= 0) ? at_bb[q] : 0.f);
    }
}

__global__ void k_c0(const float* __restrict__ leaf_U, const float* __restrict__ leaf_h,
                     const float* __restrict__ leaf_b) {
    int j = threadIdx.x;
    if (j >= JPAD) return;
    int row, q; colmap(j, row, q);
    float v = 0.f;
    if (row >= 0) {
        v = leaf_b[row];
        for (int n = 0; n < MEM; n++) v += leaf_U[row * 150 + n] * leaf_h[n];
    }
    g_c0[j] = v;
}

// ---------------- tiled GEMM ----------------
// mode 0: g_stat[n][j]    = [w|tag][n] @ WcombT + bias     (M=N, K=320)
// mode 1: g_leafpre[l][j] = [w|tag][lids[l]] @ leafWT + c0 (M=L, K=320)
// mode 2: g_kpre[lids[l]][j] = K_leaf[l] @ WkT             (M=L, K=160)
#define BM 64
#define BN 64
#define BK 16
__global__ void __launch_bounds__(256) k_gemm(int mode, int M, int Ktot,
                                              const float* __restrict__ w_emb,
                                              const float* __restrict__ tag_emb,
                                              const int* __restrict__ lids) {
    __shared__ float As[BK][BM + 4];
    __shared__ float Bs[BK][BN];
    const float* B = (mode == 0) ? g_WcombT : ((mode == 1) ? g_leafWT : g_WkT);
    int tid = threadIdx.x;
    int tx = tid & 15, ty = tid >> 4;
    int m0 = blockIdx.x * BM, j0 = blockIdx.y * BN;
    int ka = tid & 15, ma = tid >> 4;
    int jb = tid & 63, kb = tid >> 6;
    float acc[4][4] = {};
    for (int k0 = 0; k0 < Ktot; k0 += BK) {
        #pragma unroll
        for (int it = 0; it < 4; it++) {
            int r = m0 + ma + 16 * it;
            if (r >= M) r = M - 1;
            int row = (mode >= 1) ? lids[r] : r;
            int i = k0 + ka;
            float av;
            if (mode == 2) av = (i < 150) ? g_state[row * MEM + i] : 0.f;
            else av = (i < 300) ? w_emb[row * 300 + i] : tag_emb[row * 20 + (i - 300)];
            As[ka][ma + 16 * it] = av;
        }
        #pragma unroll
        for (int it = 0; it < 4; it++)
            Bs[kb + 4 * it][jb] = B[(k0 + kb + 4 * it) * JPAD + (j0 + jb)];
        __syncthreads();
        #pragma unroll
        for (int k = 0; k < BK; k++) {
            float4 a4 = *(const float4*)&As[k][ty * 4];
            float4 b4 = *(const float4*)&Bs[k][tx * 4];
            float av[4] = {a4.x, a4.y, a4.z, a4.w};
            float bv[4] = {b4.x, b4.y, b4.z, b4.w};
            #pragma unroll
            for (int mm = 0; mm < 4; mm++)
                #pragma unroll
                for (int jj = 0; jj < 4; jj++)
                    acc[mm][jj] = fmaf(av[mm], bv[jj], acc[mm][jj]);
        }
        __syncthreads();
    }
    #pragma unroll
    for (int mm = 0; mm < 4; mm++) {
        int r = m0 + ty * 4 + mm;
        if (r >= M) continue;
        #pragma unroll
        for (int jj = 0; jj < 4; jj++) {
            int j = j0 + tx * 4 + jj;
            if (mode == 0)      g_stat[r * JPAD + j]    = acc[mm][jj] + g_bias[j];
            else if (mode == 1) g_leafpre[r * JPAD + j] = acc[mm][jj] + g_c0[j];
            else                g_kpre[(size_t)lids[r] * JPAD + j] = acc[mm][jj];
        }
    }
}

// ---------------- rel projection (K=20) ----------------
__global__ void __launch_bounds__(512) k_relpart(const float* __restrict__ rel_emb) {
    int n = blockIdx.x, j = threadIdx.x;
    float acc = 0.f;
    #pragma unroll
    for (int q = 0; q < 20; q++)
        acc = fmaf(g_WrelT[q * JPAD + j], __ldg(&rel_emb[n * 20 + q]), acc);
    g_rel[n * JPAD + j] = acc;
}

// ---------------- leaf epilogue ----------------
__global__ void k_leafcomb(const int* __restrict__ lids, const float* __restrict__ leaf_h, int L) {
    int idx = blockIdx.x * blockDim.x + threadIdx.x;
    if (idx >= L * MEM) return;
    int l = idx / MEM, m = idx % MEM;
    float z  = sigf (g_leafpre[l * JPAD + m]);
    float r  = sigf (g_leafpre[l * JPAD + 160 + m]);
    float ht = tanhf(g_leafpre[l * JPAD + 320 + m]);
    g_state[lids[l] * MEM + m] = r * leaf_h[m] + (1.f - z) * ht;
}

__global__ void k_leafready(const int* __restrict__ lids, int L) {
    int l = blockIdx.x * blockDim.x + threadIdx.x;
    if (l < L) g_child_ready[lids[l]] = 2;         // 2 = leaf (kpre valid)
}

// ---------------- persistent cluster-4 chain-based edge kernel --------------
// roles 0/1/2: z/r/ht gate CTAs (160 cols); role 3: attention (32 cols)
// One ticket = one first-child chain, processed bottom-up. Chain transitions
// stay in SMEM (no global state, no flags). Only chain tops publish + release.
__global__ void __launch_bounds__(160, 1) __cluster_dims__(4, 1, 1)
k_edges(const int* __restrict__ ed,
        const float* __restrict__ at_Wa, const float* __restrict__ at_ba) {
    extern __shared__ char smem[];
    volatile int*   tick_sh = (volatile int*)(smem + OFF_TICK);
    volatile float* sa_sh   = (volatile float*)(smem + OFF_SA);
    volatile int*   sval_sh = (volatile int*)(smem + OFF_SVAL);
    float*  gatebuf = (float*)(smem + OFF_GATE);   // [2][480]
    float*  vsm  = (float*)(smem + OFF_VSM);
    float4* vsm4 = (float4*)vsm;
    float4* sw4  = (float4*)(smem + OFF_W);
    uint32_t base = smem_u32(smem);

    int tid = threadIdx.x;
    int role = (int)cluster_rank();

    // persistent weight slice into SMEM
    if (role < 3) {
        int j0 = role * 160;
        for (int r = 0; r < 76; r++)
            sw4[r * 160 + tid] = g_dyn4[r * JPAD + j0 + tid];
    } else if (tid < 32) {
        for (int r = 38; r < 76; r++)
            sw4[(r - 38) * 32 + tid] = g_dyn4[r * JPAD + 480 + tid];
    }
    if (tid < 4) vsm[150 + (tid >> 1) * 152 + (tid & 1)] = 0.f;  // pads 150,151,302,303
    __syncthreads();

    // broadcast-address setup
    float ba = 0.f, wa = 0.f;
    uint32_t remG0 = 0, remG1 = 0, remG2 = 0, remG3 = 0;
    uint32_t remS0 = 0, remS1 = 0, remS2 = 0;
    uint32_t remT0 = 0, remT1 = 0, remT2 = 0, remT3 = 0;
    if (role < 3) {
        uint32_t off = (uint32_t)(OFF_GATE) + (uint32_t)(role * 160 + tid) * 4u;
        remG0 = mapa_rank(base + off, 0);
        remG1 = mapa_rank(base + off, 1);
        remG2 = mapa_rank(base + off, 2);
        remG3 = mapa_rank(base + off, 3);
    } else {
        ba = *at_ba;
        wa = (tid < 20) ? at_Wa[tid] : 0.f;
        if (tid == 0) {
            remS0 = mapa_rank(base + OFF_SA, 0);
            remS1 = mapa_rank(base + OFF_SA, 1);
            remS2 = mapa_rank(base + OFF_SA, 2);
        }
    }
    if (role == 0 && tid == 0) {
        remT0 = mapa_rank(base + OFF_TICK, 0);
        remT1 = mapa_rank(base + OFF_TICK, 1);
        remT2 = mapa_rank(base + OFF_TICK, 2);
        remT3 = mapa_rank(base + OFF_TICK, 3);
        int e0 = atomicAdd(&g_ticket, 1);          // bootstrap -> slot 0
        st_remote_b32(remT0, (uint32_t)e0);
        st_remote_b32(remT1, (uint32_t)e0);
        st_remote_b32(remT2, (uint32_t)e0);
        st_remote_b32(remT3, (uint32_t)e0);
    }
    cluster_sync2();

    int P = g_P;
    int pathpar = 0, epar = 0;

    while (true) {
        int r = tick_sh[pathpar];
        if (r >= P) break;
        if (role == 0 && tid == 0) {               // prefetch next chain ticket
            int rn = atomicAdd(&g_ticket, 1);
            uint32_t off = 4u * (uint32_t)(pathpar ^ 1);
            st_remote_b32(remT0 + off, (uint32_t)rn);
            st_remote_b32(remT1 + off, (uint32_t)rn);
            st_remote_b32(remT2 + off, (uint32_t)rn);
            st_remote_b32(remT3 + off, (uint32_t)rn);
        }
        int t = __ldg(&g_path_top[r]);

        // walk the first-child chain to its bottom internal node
        int v = t;
        while (true) {
            int d = __ldg(&g_desig[v]);
            if (__ldg(&g_run_of[d]) < 0) break;
            v = d;
        }
        int cache_id = -1;

        // process chain bottom-up
        while (true) {
            int rid = __ldg(&g_run_of[v]);
            int es = __ldg(&g_run_start[rid]), ee = __ldg(&g_run_start[rid + 1]);

            float statv = 0.f;
            if (role < 3)       statv = __ldcg(&g_stat[(size_t)v * JPAD + role * 160 + tid]);
            else if (tid < 32)  statv = __ldcg(&g_stat[(size_t)v * JPAD + 480 + tid]);

            bool first = true;
            float hreg = 0.f;

            for (int e = es; e < ee; e++) {
                int c = __ldcg(&ed[2 * e + 1]);
                float relv = 0.f;
                if (role < 3)      relv = __ldcg(&g_rel[(size_t)c * JPAD + role * 160 + tid]);
                else if (tid < 32) relv = __ldcg(&g_rel[(size_t)c * JPAD + 480 + tid]);
                float acc = statv + relv;

                // h-half matvec (non-first edges; overlaps child wait below)
                if (!first && role < 3) {
                    const float4* wp = sw4 + tid;
                    #pragma unroll 4
                    for (int r2 = 0; r2 < 38; r2++) {
                        float4 w = wp[r2 * 160]; float4 v4 = vsm4[r2];
                        acc += w.x * v4.x + w.y * v4.y + w.z * v4.z + w.w * v4.w;
                    }
                }

                bool cached = (c == cache_id);
                int sv = 0;
                if (!cached) {
                    if (tid == 0) {
                        int vv, n = 0;
                        while (!(vv = ld_acq(&g_child_ready[c]))) { if (++n > 16) __nanosleep(64); }
                        *sval_sh = vv;
                    }
                    __syncthreads();
                    sv = *sval_sh;
                }

                if (cached || sv != 2) {
                    if (!cached) {                 // internal child from global
                        if (tid < 150) vsm[152 + tid] = __ldcg(&g_state[c * MEM + tid]);
                        __syncthreads();
                    }
                    if (role < 3) {
                        const float4* wp = sw4 + tid;
                        #pragma unroll 4
                        for (int r2 = 38; r2 < 76; r2++) {
                            float4 w = wp[r2 * 160]; float4 v4 = vsm4[r2];
                            acc += w.x * v4.x + w.y * v4.y + w.z * v4.z + w.w * v4.w;
                        }
                    } else if (tid < 32) {
                        const float4* wp = sw4 + tid;
                        #pragma unroll 4
                        for (int r2 = 38; r2 < 76; r2++) {
                            float4 w = wp[(r2 - 38) * 32]; float4 v4 = vsm4[r2];
                            acc += w.x * v4.x + w.y * v4.y + w.z * v4.z + w.w * v4.w;
                        }
                    }
                } else {                           // leaf child: precomputed k-contrib
                    if (role < 3)      acc += __ldcg(&g_kpre[(size_t)c * JPAD + role * 160 + tid]);
                    else if (tid < 32) acc += __ldcg(&g_kpre[(size_t)c * JPAD + 480 + tid]);
                }

                // broadcast gates / attention scalar to all CTAs
                if (role < 3) {
                    if (tid < 150) {
                        float gv = (role == 2) ? tanhf(acc) : sigf(acc);
                        uint32_t u = __float_as_uint(gv);
                        uint32_t soff = (uint32_t)(epar * 480) * 4u;
                        st_remote_b32(remG0 + soff, u);
                        st_remote_b32(remG1 + soff, u);
                        st_remote_b32(remG2 + soff, u);
                        st_remote_b32(remG3 + soff, u);
                    }
                } else {
                    float av = (tid < 20) ? wa * tanhf(acc) : 0.f;
                    if (tid < 32) {
                        #pragma unroll
                        for (int o = 16; o; o >>= 1) av += __shfl_down_sync(0xffffffffu, av, o);
                        if (tid == 0) {
                            float a = sigf(av + ba);
                            uint32_t u = __float_as_uint(a);
                            uint32_t soff = 4u * (uint32_t)epar;
                            sa_sh[epar] = a;
                            st_remote_b32(remS0 + soff, u);
                            st_remote_b32(remS1 + soff, u);
                            st_remote_b32(remS2 + soff, u);
                        }
                    }
                }
                cluster_sync2();                   // gates + a delivered everywhere

                // local combine (every CTA keeps its own h copy)
                float a = sa_sh[epar];
                if (tid < 150) {
                    const float* gb = gatebuf + epar * 480;
                    float z = gb[tid], r_ = gb[160 + tid], ht = gb[320 + tid];
                    float h = first ? 0.f : vsm[tid];
                    float m = r_ * h + (1.f - z) * ht;
                    hreg = a * m + (1.f - a) * h;
                    vsm[tid] = hreg;
                }
                __syncthreads();
                first = false;
                epar ^= 1;
            }

            if (v == t) {                          // chain top: publish + release
                if (role == 3) {
                    if (tid < 150) g_state[v * MEM + tid] = hreg;
                    __threadfence();
                    __syncthreads();
                    if (tid == 0) st_rel(&g_child_ready[v], 1);
                }
                break;
            }
            // chain transition: parent's first edge consumes K[v] from SMEM
            if (tid < 150) vsm[152 + tid] = hreg;
            __syncthreads();
            cache_id = v;
            v = __ldg(&g_parent_of[v]);
        }
        pathpar ^= 1;
    }
    cluster_sync2();
}

__global__ void k_out(float* __restrict__ out) {
    int m = threadIdx.x;
    if (m < MEM) out[m] = g_state[m];
}

// ---------------- launch ----------------
extern "C" void kernel_launch(void* const* d_in, const int* in_sizes, int n_in,
                              void* d_out, int out_size) {
    const float* w_emb   = (const float*)d_in[0];
    const float* tag_emb = (const float*)d_in[1];
    const float* rel_emb = (const float*)d_in[2];
    const float* leaf_h  = (const float*)d_in[3];
    const float* leaf_W  = (const float*)d_in[4];
    const float* leaf_U  = (const float*)d_in[5];
    const float* leaf_b  = (const float*)d_in[6];
    const float* node_W  = (const float*)d_in[7];
    const float* node_U  = (const float*)d_in[8];
    const float* node_b  = (const float*)d_in[9];
    const float* at_Wb   = (const float*)d_in[10];
    const float* at_bb   = (const float*)d_in[11];
    const float* at_Wa   = (const float*)d_in[12];
    const float* at_ba   = (const float*)d_in[13];
    const int*   edges   = (const int*)d_in[14];
    const int*   lids    = (const int*)d_in[15];

    int N = in_sizes[0] / 300;
    int E = in_sizes[14] / 2;
    int L = in_sizes[15];

    cudaFuncSetAttribute(k_edges, cudaFuncAttributeMaxDynamicSharedMemorySize, EDGE_SMEM);

    k_init<<<64, 256>>>(N, E);
    k_runscan<<<1, 1024>>>(edges, E);
    k_parent<<<(E + 255) / 256, 256>>>(edges, E);
    k_pathscan<<<1, 1024>>>(N);
    k_build_big<<<(320 * JPAD + 255) / 256, 256>>>(node_W, node_U, at_Wb, leaf_W);
    k_build_small<<<(21 * JPAD + 255) / 256, 256>>>(node_W, at_Wb, node_b, at_bb);
    k_c0<<<1, 512>>>(leaf_U, leaf_h, leaf_b);
    k_gemm<<<dim3((N + BM - 1) / BM, JPAD / BN), 256>>>(0, N, 320, w_emb, tag_emb, lids);
    k_gemm<<<dim3((L + BM - 1) / BM, JPAD / BN), 256>>>(1, L, 320, w_emb, tag_emb, lids);
    k_relpart<<<N, 512>>>(rel_emb);
    k_leafcomb<<<(L * MEM + 255) / 256, 256>>>(lids, leaf_h, L);
    k_gemm<<<dim3((L + BM - 1) / BM, JPAD / BN), 256>>>(2, L, 160, w_emb, tag_emb, lids);
    k_leafready<<<(L + 255) / 256, 256>>>(lids, L);
    k_edges<<<4 * NCLUST, 160, EDGE_SMEM>>>(edges, at_Wa, at_ba);
    k_out<<<1, 256>>>((float*)d_out);
}

// round 11
// speedup vs baseline: 2.1505x; 1.1194x over previous
#include <cuda_runtime.h>
#include <cuda_bf16.h>
#include <cstdint>

#define MAXN 32768
#define MAXE 32768
#define MEM  150
#define JPAD 512
#define NCLUST 33

// ---- shared-memory byte offsets (same layout in every CTA) ----
#define OFF_GMB     0               // 2 gate mbarriers (8B each)
#define OFF_TMB     16              // 2 ticket mbarriers
#define OFF_TICKBUF 32              // 2 ints (double-buffered ticket)
#define OFF_SA      40              // 2 floats (double-buffered attention scalar)
#define OFF_SVAL    48              // int (child-ready value)
#define OFF_GATE    64              // 2 slots * 480 floats -> [64, 3904)
#define OFF_VSM     3904            // 304 floats (h 0..151 | k 152..303), 16B aligned
#define OFF_W       5120            // 76*160 float4 = 194560B
#define EDGE_SMEM   (OFF_W + 76*160*16)
#define GATE_TX     1804            // 3*150*4 gate bytes + 4 bytes attention scalar

// ---------------- static device scratch (no allocations allowed) ------------
__device__ float g_state[MAXN * MEM];            // node K (published for chain tops + leaves)
__device__ float g_stat [MAXN * JPAD];           // per-node static: Ww@w + Wt@tag + bias
__device__ float g_rel  [MAXN * JPAD];           // per-node: Wrel@rel
__device__ float g_leafpre[MAXN * JPAD];         // leaf GRU pre-activations
__device__ float g_kpre [MAXN * JPAD];           // leaf nodes: Wk@K[leaf] precomputed
__device__ float g_WcombT[320 * JPAD];           // [w|tag] static weights, i-major
__device__ float g_leafWT [320 * JPAD];          // leaf_W transposed, i-major
__device__ float g_WkT   [160 * JPAD];           // k-part weights, i-major (for kpre GEMM)
__device__ float g_WrelT  [20  * JPAD];
__device__ float4 g_dyn4[76 * JPAD];             // dyn weights: vi 0..149=U(h), 152..301=Wk(k)
__device__ float g_bias[JPAD];
__device__ float g_c0[JPAD];                     // leaf: leaf_U@leaf_h + leaf_b
__device__ int   g_child_ready[MAXN];            // 0=not ready, 1=internal done, 2=leaf
__device__ int   g_run_start[MAXE + 1];
__device__ int   g_run_of[MAXN];                 // node -> run id (-1 = leaf)
__device__ int   g_desig[MAXN];                  // node -> first child (chain link)
__device__ int   g_parent_of[MAXN];              // child -> parent
__device__ int   g_path_top[MAXE];               // chain tops, node index descending
__device__ int   g_P;                            // number of chains
__device__ int   g_R;
__device__ int   g_ticket;

// ---------------- asm helpers ----------------
__device__ __forceinline__ int ld_acq(const int* p) {
    int v;
    asm volatile("ld.acquire.gpu.global.b32 %0, [%1];" : "=r"(v) : "l"(p) : "memory");
    return v;
}
__device__ __forceinline__ void st_rel(int* p, int v) {
    asm volatile("st.release.gpu.global.b32 [%0], %1;" :: "l"(p), "r"(v) : "memory");
}
__device__ __forceinline__ float sigf(float x) { return 1.f / (1.f + expf(-x)); }
__device__ __forceinline__ uint32_t smem_u32(const void* p) {
    return (uint32_t)__cvta_generic_to_shared(p);
}
__device__ __forceinline__ uint32_t cluster_rank() {
    uint32_t r; asm("mov.u32 %0, %%cluster_ctarank;" : "=r"(r)); return r;
}
__device__ __forceinline__ uint32_t mapa_rank(uint32_t addr, uint32_t rank) {
    uint32_t r;
    asm("mapa.shared::cluster.u32 %0, %1, %2;" : "=r"(r) : "r"(addr), "r"(rank));
    return r;
}
__device__ __forceinline__ void mbar_init(uint32_t a, uint32_t cnt) {
    asm volatile("mbarrier.init.shared.b64 [%0], %1;" :: "r"(a), "r"(cnt) : "memory");
}
__device__ __forceinline__ void mbar_expect_tx(uint32_t a, uint32_t bytes) {
    asm volatile("mbarrier.arrive.expect_tx.shared.b64 _, [%0], %1;" :: "r"(a), "r"(bytes) : "memory");
}
// remote store with transaction accounting on the DESTINATION CTA's mbarrier
__device__ __forceinline__ void st_async_b32(uint32_t remAddr, uint32_t v, uint32_t remMbar) {
    asm volatile("st.async.shared::cluster.mbarrier::complete_tx::bytes.b32 [%0], %1, [%2];"
                 :: "r"(remAddr), "r"(v), "r"(remMbar) : "memory");
}
__device__ __forceinline__ void mbar_wait(uint32_t a, uint32_t parity) {
    uint32_t done;
    do {
        asm volatile(
            "{\n\t.reg .pred p;\n\t"
            "mbarrier.try_wait.parity.acquire.cluster.shared::cta.b64 p, [%1], %2, 0x989680;\n\t"
            "selp.b32 %0, 1, 0, p;\n\t}"
            : "=r"(done) : "r"(a), "r"(parity) : "memory");
    } while (!done);
}
__device__ __forceinline__ void cluster_sync2() {
    asm volatile("barrier.cluster.arrive.aligned;" ::: "memory");
    asm volatile("barrier.cluster.wait.aligned;" ::: "memory");
}

// column -> (gru row | att row) mapping
__device__ __forceinline__ void colmap(int j, int& row, int& q) {
    row = -1; q = -1;
    if (j < 480) { int m = j % 160; if (m < 150) row = (j / 160) * 150 + m; }
    else if (j < 500) q = j - 480;
}

// ---------------- init ----------------
__global__ void k_init(int N, int E) {
    int stride = gridDim.x * blockDim.x;
    int t0 = blockIdx.x * blockDim.x + threadIdx.x;
    for (int i = t0; i < N; i += stride) { g_child_ready[i] = 0; g_run_of[i] = -1; }
    if (t0 == 0) g_ticket = 0;
}

// ---------------- run table (single block scan) ----------------
__global__ void k_runscan(const int* __restrict__ ed, int E) {
    __shared__ int sflag[1024];
    __shared__ int sbase;
    int tid = threadIdx.x;
    if (tid == 0) sbase = 0;
    __syncthreads();
    for (int chunk = 0; chunk < E; chunk += 1024) {
        int i = chunk + tid;
        int f = 0;
        if (i < E) f = (i == 0) || (ed[2 * i] != ed[2 * i - 2]);
        sflag[tid] = f;
        __syncthreads();
        for (int off = 1; off < 1024; off <<= 1) {
            int v = (tid >= off) ? sflag[tid - off] : 0;
            __syncthreads();
            sflag[tid] += v;
            __syncthreads();
        }
        if (i < E && f) {
            int rid = sbase + sflag[tid] - 1;
            int p = ed[2 * i];
            g_run_start[rid] = i;
            g_run_of[p] = rid;
            g_desig[p] = ed[2 * i + 1];            // first child = chain link
        }
        __syncthreads();
        if (tid == 0) sbase += sflag[1023];
        __syncthreads();
    }
    if (tid == 0) { g_R = sbase; g_run_start[sbase] = E; }
}

// ---------------- parent map ----------------
__global__ void k_parent(const int* __restrict__ ed, int E) {
    int i = blockIdx.x * blockDim.x + threadIdx.x;
    if (i < E) g_parent_of[ed[2 * i + 1]] = ed[2 * i];
    if (i == 0) g_parent_of[0] = -1;
}

// ---------------- chain tops, node index descending (single block scan) -----
__global__ void k_pathscan(int N) {
    __shared__ int sflag[1024];
    __shared__ int sbase;
    int tid = threadIdx.x;
    if (tid == 0) sbase = 0;
    __syncthreads();
    for (int chunk = 0; chunk < N; chunk += 1024) {
        int nr = chunk + tid;
        int n = N - 1 - nr;
        int f = 0;
        if (nr < N && g_run_of[n] >= 0) {          // internal node
            if (n == 0) f = 1;
            else f = (g_desig[g_parent_of[n]] != n) ? 1 : 0;   // not chain-linked
        }
        sflag[tid] = f;
        __syncthreads();
        for (int off = 1; off < 1024; off <<= 1) {
            int v = (tid >= off) ? sflag[tid - off] : 0;
            __syncthreads();
            sflag[tid] += v;
            __syncthreads();
        }
        if (f) g_path_top[sbase + sflag[tid] - 1] = n;
        __syncthreads();
        if (tid == 0) sbase += sflag[1023];
        __syncthreads();
    }
    if (tid == 0) g_P = sbase;
}

// ---------------- weight reshuffles ----------------
// node_W: (450,490), x layout: [word 0..299 | K 300..449 | rel 450..469 | tag 470..489]
__global__ void k_build_big(const float* __restrict__ node_W, const float* __restrict__ node_U,
                            const float* __restrict__ at_Wb,  const float* __restrict__ leaf_W) {
    int idx = blockIdx.x * blockDim.x + threadIdx.x;
    if (idx >= 320 * JPAD) return;
    int i = idx / JPAD, j = idx % JPAD;
    int row, q; colmap(j, row, q);
    float v = 0.f;
    if (row >= 0)      v = (i < 300) ? node_W[row * 490 + i] : node_W[row * 490 + 470 + (i - 300)];
    else if (q >= 0)   v = (i < 300) ? at_Wb[q * 490 + i]    : at_Wb[q * 490 + 470 + (i - 300)];
    g_WcombT[idx] = v;
    g_leafWT[idx] = (row >= 0) ? leaf_W[row * 320 + i] : 0.f;
    if (i < 304) {
        float mv = 0.f;
        if (i < 150) {
            if (row >= 0) mv = node_U[row * 150 + i];
        } else if (i >= 152 && i < 302) {
            int kk = i - 152;
            if (row >= 0)      mv = node_W[row * 490 + 300 + kk];
            else if (q >= 0)   mv = at_Wb[q * 490 + 300 + kk];
        }
        reinterpret_cast<float*>(g_dyn4)[((i >> 2) * JPAD + j) * 4 + (i & 3)] = mv;
    }
    if (i < 160) {
        float kv = 0.f;
        if (i < 150) {
            if (row >= 0)      kv = node_W[row * 490 + 300 + i];
            else if (q >= 0)   kv = at_Wb[q * 490 + 300 + i];
        }
        g_WkT[i * JPAD + j] = kv;
    }
}

__global__ void k_build_small(const float* __restrict__ node_W, const float* __restrict__ at_Wb,
                              const float* __restrict__ node_b, const float* __restrict__ at_bb) {
    int idx = blockIdx.x * blockDim.x + threadIdx.x;
    if (idx < 20 * JPAD) {
        int i = idx / JPAD, j = idx % JPAD;
        int row, q; colmap(j, row, q);
        float v = 0.f;
        if (row >= 0)    v = node_W[row * 490 + 450 + i];
        else if (q >= 0) v = at_Wb[q * 490 + 450 + i];
        g_WrelT[idx] = v;
    } else if (idx < 21 * JPAD) {
        int j = idx - 20 * JPAD;
        int row, q; colmap(j, row, q);
        g_bias[j] = (row >= 0) ? node_b[row] : ((q >= 0) ? at_bb[q] : 0.f);
    }
}

__global__ void k_c0(const float* __restrict__ leaf_U, const float* __restrict__ leaf_h,
                     const float* __restrict__ leaf_b) {
    int j = threadIdx.x;
    if (j >= JPAD) return;
    int row, q; colmap(j, row, q);
    float v = 0.f;
    if (row >= 0) {
        v = leaf_b[row];
        for (int n = 0; n < MEM; n++) v += leaf_U[row * 150 + n] * leaf_h[n];
    }
    g_c0[j] = v;
}

// ---------------- tiled GEMM ----------------
// mode 0: g_stat[n][j]    = [w|tag][n] @ WcombT + bias     (M=N, K=320)
// mode 1: g_leafpre[l][j] = [w|tag][lids[l]] @ leafWT + c0 (M=L, K=320)
// mode 2: g_kpre[lids[l]][j] = K_leaf[l] @ WkT             (M=L, K=160)
#define BM 64
#define BN 64
#define BK 16
__global__ void __launch_bounds__(256) k_gemm(int mode, int M, int Ktot,
                                              const float* __restrict__ w_emb,
                                              const float* __restrict__ tag_emb,
                                              const int* __restrict__ lids) {
    __shared__ float As[BK][BM + 4];
    __shared__ float Bs[BK][BN];
    const float* B = (mode == 0) ? g_WcombT : ((mode == 1) ? g_leafWT : g_WkT);
    int tid = threadIdx.x;
    int tx = tid & 15, ty = tid >> 4;
    int m0 = blockIdx.x * BM, j0 = blockIdx.y * BN;
    int ka = tid & 15, ma = tid >> 4;
    int jb = tid & 63, kb = tid >> 6;
    float acc[4][4] = {};
    for (int k0 = 0; k0 < Ktot; k0 += BK) {
        #pragma unroll
        for (int it = 0; it < 4; it++) {
            int r = m0 + ma + 16 * it;
            if (r >= M) r = M - 1;
            int row = (mode >= 1) ? lids[r] : r;
            int i = k0 + ka;
            float av;
            if (mode == 2) av = (i < 150) ? g_state[row * MEM + i] : 0.f;
            else av = (i < 300) ? w_emb[row * 300 + i] : tag_emb[row * 20 + (i - 300)];
            As[ka][ma + 16 * it] = av;
        }
        #pragma unroll
        for (int it = 0; it < 4; it++)
            Bs[kb + 4 * it][jb] = B[(k0 + kb + 4 * it) * JPAD + (j0 + jb)];
        __syncthreads();
        #pragma unroll
        for (int k = 0; k < BK; k++) {
            float4 a4 = *(const float4*)&As[k][ty * 4];
            float4 b4 = *(const float4*)&Bs[k][tx * 4];
            float av[4] = {a4.x, a4.y, a4.z, a4.w};
            float bv[4] = {b4.x, b4.y, b4.z, b4.w};
            #pragma unroll
            for (int mm = 0; mm < 4; mm++)
                #pragma unroll
                for (int jj = 0; jj < 4; jj++)
                    acc[mm][jj] = fmaf(av[mm], bv[jj], acc[mm][jj]);
        }
        __syncthreads();
    }
    #pragma unroll
    for (int mm = 0; mm < 4; mm++) {
        int r = m0 + ty * 4 + mm;
        if (r >= M) continue;
        #pragma unroll
        for (int jj = 0; jj < 4; jj++) {
            int j = j0 + tx * 4 + jj;
            if (mode == 0)      g_stat[r * JPAD + j]    = acc[mm][jj] + g_bias[j];
            else if (mode == 1) g_leafpre[r * JPAD + j] = acc[mm][jj] + g_c0[j];
            else                g_kpre[(size_t)lids[r] * JPAD + j] = acc[mm][jj];
        }
    }
}

// ---------------- rel projection (K=20) ----------------
__global__ void __launch_bounds__(512) k_relpart(const float* __restrict__ rel_emb) {
    int n = blockIdx.x, j = threadIdx.x;
    float acc = 0.f;
    #pragma unroll
    for (int q = 0; q < 20; q++)
        acc = fmaf(g_WrelT[q * JPAD + j], __ldg(&rel_emb[n * 20 + q]), acc);
    g_rel[n * JPAD + j] = acc;
}

// ---------------- leaf epilogue ----------------
__global__ void k_leafcomb(const int* __restrict__ lids, const float* __restrict__ leaf_h, int L) {
    int idx = blockIdx.x * blockDim.x + threadIdx.x;
    if (idx >= L * MEM) return;
    int l = idx / MEM, m = idx % MEM;
    float z  = sigf (g_leafpre[l * JPAD + m]);
    float r  = sigf (g_leafpre[l * JPAD + 160 + m]);
    float ht = tanhf(g_leafpre[l * JPAD + 320 + m]);
    g_state[lids[l] * MEM + m] = r * leaf_h[m] + (1.f - z) * ht;
}

__global__ void k_leafready(const int* __restrict__ lids, int L) {
    int l = blockIdx.x * blockDim.x + threadIdx.x;
    if (l < L) g_child_ready[lids[l]] = 2;         // 2 = leaf (kpre valid)
}

// ---------------- persistent cluster-4 chain kernel, st.async rendezvous ----
// roles 0/1/2: z/r/ht gate CTAs (160 cols); role 3: attention (32 cols)
// Per edge: workers st.async gates to ALL CTAs (tx-counted), role3 st.async the
// attention scalar; every CTA try_waits its own gate mbarrier (no cluster.sync).
__global__ void __launch_bounds__(160, 1) __cluster_dims__(4, 1, 1)
k_edges(const int* __restrict__ ed,
        const float* __restrict__ at_Wa, const float* __restrict__ at_ba) {
    extern __shared__ char smem[];
    volatile int*   tickbuf = (volatile int*)(smem + OFF_TICKBUF);
    volatile float* sa_sh   = (volatile float*)(smem + OFF_SA);
    volatile int*   sval_sh = (volatile int*)(smem + OFF_SVAL);
    float*  gatebuf = (float*)(smem + OFF_GATE);   // [2][480]
    float*  vsm  = (float*)(smem + OFF_VSM);
    float4* vsm4 = (float4*)vsm;
    float4* sw4  = (float4*)(smem + OFF_W);
    uint32_t base = smem_u32(smem);

    int tid = threadIdx.x;
    int role = (int)cluster_rank();

    // persistent weight slice into SMEM
    if (role < 3) {
        int j0 = role * 160;
        for (int r = 0; r < 76; r++)
            sw4[r * 160 + tid] = g_dyn4[r * JPAD + j0 + tid];
    } else if (tid < 32) {
        for (int r = 38; r < 76; r++)
            sw4[(r - 38) * 32 + tid] = g_dyn4[r * JPAD + 480 + tid];
    }
    if (tid < 4) vsm[150 + (tid >> 1) * 152 + (tid & 1)] = 0.f;  // pads 150,151,302,303
    __syncthreads();

    // mbarrier init + initial arming (count=1; the expect_tx arrive is the arrival)
    if (tid == 0) {
        mbar_init(base + OFF_GMB, 1);      mbar_init(base + OFF_GMB + 8, 1);
        mbar_init(base + OFF_TMB, 1);      mbar_init(base + OFF_TMB + 8, 1);
    }
    __syncthreads();
    if (tid == 0) {
        mbar_expect_tx(base + OFF_GMB,     GATE_TX);
        mbar_expect_tx(base + OFF_GMB + 8, GATE_TX);
        mbar_expect_tx(base + OFF_TMB,     4);
        mbar_expect_tx(base + OFF_TMB + 8, 4);
    }
    __syncthreads();

    uint32_t rb0 = mapa_rank(base, 0), rb1 = mapa_rank(base, 1);
    uint32_t rb2 = mapa_rank(base, 2), rb3 = mapa_rank(base, 3);

    float ba = 0.f, wa = 0.f;
    if (role == 3) { ba = *at_ba; wa = (tid < 20) ? at_Wa[tid] : 0.f; }

    cluster_sync2();                               // all barriers armed cluster-wide

    if (role == 0 && tid == 0) {                   // bootstrap ticket -> slot 0
        int e0 = atomicAdd(&g_ticket, 1);
        st_async_b32(rb0 + OFF_TICKBUF, (uint32_t)e0, rb0 + OFF_TMB);
        st_async_b32(rb1 + OFF_TICKBUF, (uint32_t)e0, rb1 + OFF_TMB);
        st_async_b32(rb2 + OFF_TICKBUF, (uint32_t)e0, rb2 + OFF_TMB);
        st_async_b32(rb3 + OFF_TICKBUF, (uint32_t)e0, rb3 + OFF_TMB);
    }

    int P = g_P;
    int epar = 0;
    uint32_t gph0 = 0, gph1 = 0;
    int tslot = 0; uint32_t tph0 = 0, tph1 = 0;

    while (true) {
        // ---- ticket rendezvous ----
        uint32_t tmbL = base + OFF_TMB + 8u * (uint32_t)tslot;
        mbar_wait(tmbL, tslot ? tph1 : tph0);
        if (tslot) tph1 ^= 1; else tph0 ^= 1;
        int r = tickbuf[tslot];
        __syncthreads();                           // all read before re-arm
        if (tid == 0) mbar_expect_tx(tmbL, 4);     // arm for ticket (this_seq + 2)
        if (r >= P) break;
        bool sendNext = (role == 0 && tid == 0);
        tslot ^= 1;                                // next ticket (and send target) slot

        int t = __ldg(&g_path_top[r]);
        int v = t;
        while (true) {
            int d = __ldg(&g_desig[v]);
            if (__ldg(&g_run_of[d]) < 0) break;
            v = d;
        }
        int cache_id = -1;

        while (true) {                             // chain bottom-up
            int rid = __ldg(&g_run_of[v]);
            int es = __ldg(&g_run_start[rid]), ee = __ldg(&g_run_start[rid + 1]);

            float statv = 0.f;
            if (role < 3)       statv = __ldcg(&g_stat[(size_t)v * JPAD + role * 160 + tid]);
            else if (tid < 32)  statv = __ldcg(&g_stat[(size_t)v * JPAD + 480 + tid]);

            bool first = true;
            float hreg = 0.f;

            for (int e = es; e < ee; e++) {
                int c = __ldcg(&ed[2 * e + 1]);
                float relv = 0.f;
                if (role < 3)      relv = __ldcg(&g_rel[(size_t)c * JPAD + role * 160 + tid]);
                else if (tid < 32) relv = __ldcg(&g_rel[(size_t)c * JPAD + 480 + tid]);
                float acc = statv + relv;

                // h-half matvec (non-first edges)
                if (!first && role < 3) {
                    const float4* wp = sw4 + tid;
                    #pragma unroll 4
                    for (int r2 = 0; r2 < 38; r2++) {
                        float4 w = wp[r2 * 160]; float4 v4 = vsm4[r2];
                        acc += w.x * v4.x + w.y * v4.y + w.z * v4.z + w.w * v4.w;
                    }
                }

                bool cached = (c == cache_id);
                int sv = 0;
                if (!cached) {
                    if (tid == 0) {
                        int vv, n = 0;
                        while (!(vv = ld_acq(&g_child_ready[c]))) { if (++n > 16) __nanosleep(64); }
                        *sval_sh = vv;
                    }
                    __syncthreads();
                    sv = *sval_sh;
                }

                if (cached || sv != 2) {
                    if (!cached) {
                        if (tid < 150) vsm[152 + tid] = __ldcg(&g_state[c * MEM + tid]);
                        __syncthreads();
                    }
                    if (role < 3) {
                        const float4* wp = sw4 + tid;
                        #pragma unroll 4
                        for (int r2 = 38; r2 < 76; r2++) {
                            float4 w = wp[r2 * 160]; float4 v4 = vsm4[r2];
                            acc += w.x * v4.x + w.y * v4.y + w.z * v4.z + w.w * v4.w;
                        }
                    } else if (tid < 32) {
                        const float4* wp = sw4 + tid;
                        #pragma unroll 4
                        for (int r2 = 38; r2 < 76; r2++) {
                            float4 w = wp[(r2 - 38) * 32]; float4 v4 = vsm4[r2];
                            acc += w.x * v4.x + w.y * v4.y + w.z * v4.z + w.w * v4.w;
                        }
                    }
                } else {                           // leaf child: precomputed k-contrib
                    if (role < 3)      acc += __ldcg(&g_kpre[(size_t)c * JPAD + role * 160 + tid]);
                    else if (tid < 32) acc += __ldcg(&g_kpre[(size_t)c * JPAD + 480 + tid]);
                }

                // ---- deliver gates / attention scalar via st.async ----
                uint32_t boff = (uint32_t)OFF_GMB + 8u * (uint32_t)epar;
                if (role < 3) {
                    if (tid < 150) {
                        float gv = (role == 2) ? tanhf(acc) : sigf(acc);
                        uint32_t u = __float_as_uint(gv);
                        uint32_t doff = (uint32_t)OFF_GATE
                                      + (uint32_t)(epar * 480 + role * 160 + tid) * 4u;
                        st_async_b32(rb0 + doff, u, rb0 + boff);
                        st_async_b32(rb1 + doff, u, rb1 + boff);
                        st_async_b32(rb2 + doff, u, rb2 + boff);
                        st_async_b32(rb3 + doff, u, rb3 + boff);
                    }
                } else {
                    float av = (tid < 20) ? wa * tanhf(acc) : 0.f;
                    if (tid < 32) {
                        #pragma unroll
                        for (int o = 16; o; o >>= 1) av += __shfl_down_sync(0xffffffffu, av, o);
                        if (tid == 0) {
                            float a = sigf(av + ba);
                            uint32_t u = __float_as_uint(a);
                            uint32_t doff = (uint32_t)OFF_SA + 4u * (uint32_t)epar;
                            st_async_b32(rb0 + doff, u, rb0 + boff);
                            st_async_b32(rb1 + doff, u, rb1 + boff);
                            st_async_b32(rb2 + doff, u, rb2 + boff);
                            st_async_b32(rb3 + doff, u, rb3 + boff);
                        }
                    }
                }

                // ---- local rendezvous: wait own gate mbarrier ----
                uint32_t gmbL = base + boff;
                mbar_wait(gmbL, epar ? gph1 : gph0);
                if (epar) gph1 ^= 1; else gph0 ^= 1;

                // local combine (every CTA keeps its own h copy)
                float a = sa_sh[epar];
                if (tid < 150) {
                    const float* gb = gatebuf + epar * 480;
                    float z = gb[tid], r_ = gb[160 + tid], ht = gb[320 + tid];
                    float h = first ? 0.f : vsm[tid];
                    float m = r_ * h + (1.f - z) * ht;
                    hreg = a * m + (1.f - a) * h;
                    vsm[tid] = hreg;
                }
                __syncthreads();                   // gates consumed by all threads
                if (tid == 0) mbar_expect_tx(gmbL, GATE_TX);   // re-arm for edge+2
                if (sendNext) {                    // after first rendezvous of chain
                    int rn = atomicAdd(&g_ticket, 1);
                    uint32_t tdoff = (uint32_t)OFF_TICKBUF + 4u * (uint32_t)tslot;
                    uint32_t tboff = (uint32_t)OFF_TMB + 8u * (uint32_t)tslot;
                    st_async_b32(rb0 + tdoff, (uint32_t)rn, rb0 + tboff);
                    st_async_b32(rb1 + tdoff, (uint32_t)rn, rb1 + tboff);
                    st_async_b32(rb2 + tdoff, (uint32_t)rn, rb2 + tboff);
                    st_async_b32(rb3 + tdoff, (uint32_t)rn, rb3 + tboff);
                    sendNext = false;
                }
                first = false;
                epar ^= 1;
            }

            if (v == t) {                          // chain top: publish + release
                if (role == 3) {
                    if (tid < 150) g_state[v * MEM + tid] = hreg;
                    __threadfence();
                    __syncthreads();
                    if (tid == 0) st_rel(&g_child_ready[v], 1);
                }
                break;
            }
            // chain transition: parent's first edge consumes K[v] from SMEM
            if (tid < 150) vsm[152 + tid] = hreg;
            __syncthreads();
            cache_id = v;
            v = __ldg(&g_parent_of[v]);
        }
    }
    cluster_sync2();
}

__global__ void k_out(float* __restrict__ out) {
    int m = threadIdx.x;
    if (m < MEM) out[m] = g_state[m];
}

// ---------------- launch ----------------
extern "C" void kernel_launch(void* const* d_in, const int* in_sizes, int n_in,
                              void* d_out, int out_size) {
    const float* w_emb   = (const float*)d_in[0];
    const float* tag_emb = (const float*)d_in[1];
    const float* rel_emb = (const float*)d_in[2];
    const float* leaf_h  = (const float*)d_in[3];
    const float* leaf_W  = (const float*)d_in[4];
    const float* leaf_U  = (const float*)d_in[5];
    const float* leaf_b  = (const float*)d_in[6];
    const float* node_W  = (const float*)d_in[7];
    const float* node_U  = (const float*)d_in[8];
    const float* node_b  = (const float*)d_in[9];
    const float* at_Wb   = (const float*)d_in[10];
    const float* at_bb   = (const float*)d_in[11];
    const float* at_Wa   = (const float*)d_in[12];
    const float* at_ba   = (const float*)d_in[13];
    const int*   edges   = (const int*)d_in[14];
    const int*   lids    = (const int*)d_in[15];

    int N = in_sizes[0] / 300;
    int E = in_sizes[14] / 2;
    int L = in_sizes[15];

    cudaFuncSetAttribute(k_edges, cudaFuncAttributeMaxDynamicSharedMemorySize, EDGE_SMEM);

    k_init<<<64, 256>>>(N, E);
    k_runscan<<<1, 1024>>>(edges, E);
    k_parent<<<(E + 255) / 256, 256>>>(edges, E);
    k_pathscan<<<1, 1024>>>(N);
    k_build_big<<<(320 * JPAD + 255) / 256, 256>>>(node_W, node_U, at_Wb, leaf_W);
    k_build_small<<<(21 * JPAD + 255) / 256, 256>>>(node_W, at_Wb, node_b, at_bb);
    k_c0<<<1, 512>>>(leaf_U, leaf_h, leaf_b);
    k_gemm<<<dim3((N + BM - 1) / BM, JPAD / BN), 256>>>(0, N, 320, w_emb, tag_emb, lids);
    k_gemm<<<dim3((L + BM - 1) / BM, JPAD / BN), 256>>>(1, L, 320, w_emb, tag_emb, lids);
    k_relpart<<<N, 512>>>(rel_emb);
    k_leafcomb<<<(L * MEM + 255) / 256, 256>>>(lids, leaf_h, L);
    k_gemm<<<dim3((L + BM - 1) / BM, JPAD / BN), 256>>>(2, L, 160, w_emb, tag_emb, lids);
    k_leafready<<<(L + 255) / 256, 256>>>(lids, L);
    k_edges<<<4 * NCLUST, 160, EDGE_SMEM>>>(edges, at_Wa, at_ba);
    k_out<<<1, 256>>>((float*)d_out);
}

// round 12
// speedup vs baseline: 2.5226x; 1.1730x over previous
#include <cuda_runtime.h>
#include <cuda_bf16.h>
#include <cstdint>

#define MAXN 32768
#define MAXE 32768
#define MEM  150
#define JPAD 512
#define NCLUST 33

// ---- shared-memory byte offsets (same layout in every CTA) ----
#define OFF_GMB     0               // 2 gate mbarriers (8B each)
#define OFF_TMB     16              // 2 ticket mbarriers
#define OFF_TICKBUF 32              // 2 ints (double-buffered ticket)
#define OFF_SA      40              // 2 floats (double-buffered attention scalar)
#define OFF_GATE    64              // 2 slots * 480 floats -> [64, 3904)
#define OFF_VSM     3904            // 304 floats (h 0..151 | k 152..303), 16B aligned
#define OFF_W       5120            // 76*160 float4 = 194560B
#define EDGE_SMEM   (OFF_W + 76*160*16)
#define GATE_TX     1804            // 3*150*4 gate bytes + 4 bytes attention scalar

// ---------------- static device scratch (no allocations allowed) ------------
__device__ float g_state[MAXN * MEM];            // node K (published for chain tops + leaves)
__device__ float g_stat [MAXN * JPAD];           // per-node static: Ww@w + Wt@tag + bias
__device__ float g_rel  [MAXN * JPAD];           // per-node: Wrel@rel
__device__ float g_leafpre[MAXN * JPAD];         // leaf GRU pre-activations
__device__ float g_kpre [MAXN * JPAD];           // leaf nodes: Wk@K[leaf] precomputed
__device__ float g_WcombT[320 * JPAD];           // [w|tag] static weights, i-major
__device__ float g_leafWT [320 * JPAD];          // leaf_W transposed, i-major
__device__ float g_WkT   [160 * JPAD];           // k-part weights, i-major (for kpre GEMM)
__device__ float g_WrelT  [20  * JPAD];
__device__ float4 g_dyn4[76 * JPAD];             // dyn weights: vi 0..149=U(h), 152..301=Wk(k)
__device__ float g_bias[JPAD];
__device__ float g_c0[JPAD];                     // leaf: leaf_U@leaf_h + leaf_b
__device__ int   g_child_ready[MAXN];            // 0=not ready, 1=done
__device__ int   g_run_start[MAXE + 1];
__device__ int   g_run_of[MAXN];                 // node -> run id (-1 = leaf)
__device__ int   g_desig[MAXN];                  // node -> first child (chain link)
__device__ int   g_parent_of[MAXN];              // child -> parent
__device__ int   g_echild[MAXE];                 // child | (leaf << 31)
__device__ int   g_path_top[MAXE];               // chain tops, node index descending
__device__ int   g_P;                            // number of chains
__device__ int   g_R;
__device__ int   g_ticket;

// ---------------- asm helpers ----------------
__device__ __forceinline__ int ld_acq(const int* p) {
    int v;
    asm volatile("ld.acquire.gpu.global.b32 %0, [%1];" : "=r"(v) : "l"(p) : "memory");
    return v;
}
__device__ __forceinline__ void st_rel(int* p, int v) {
    asm volatile("st.release.gpu.global.b32 [%0], %1;" :: "l"(p), "r"(v) : "memory");
}
__device__ __forceinline__ float sigf(float x) { return 1.f / (1.f + expf(-x)); }
__device__ __forceinline__ uint32_t smem_u32(const void* p) {
    return (uint32_t)__cvta_generic_to_shared(p);
}
__device__ __forceinline__ uint32_t cluster_rank() {
    uint32_t r; asm("mov.u32 %0, %%cluster_ctarank;" : "=r"(r)); return r;
}
__device__ __forceinline__ uint32_t mapa_rank(uint32_t addr, uint32_t rank) {
    uint32_t r;
    asm("mapa.shared::cluster.u32 %0, %1, %2;" : "=r"(r) : "r"(addr), "r"(rank));
    return r;
}
__device__ __forceinline__ void mbar_init(uint32_t a, uint32_t cnt) {
    asm volatile("mbarrier.init.shared.b64 [%0], %1;" :: "r"(a), "r"(cnt) : "memory");
}
__device__ __forceinline__ void mbar_expect_tx(uint32_t a, uint32_t bytes) {
    asm volatile("mbarrier.arrive.expect_tx.shared.b64 _, [%0], %1;" :: "r"(a), "r"(bytes) : "memory");
}
__device__ __forceinline__ void st_async_b32(uint32_t remAddr, uint32_t v, uint32_t remMbar) {
    asm volatile("st.async.shared::cluster.mbarrier::complete_tx::bytes.b32 [%0], %1, [%2];"
                 :: "r"(remAddr), "r"(v), "r"(remMbar) : "memory");
}
__device__ __forceinline__ void mbar_wait(uint32_t a, uint32_t parity) {
    uint32_t done;
    do {
        asm volatile(
            "{\n\t.reg .pred p;\n\t"
            "mbarrier.try_wait.parity.acquire.cluster.shared::cta.b64 p, [%1], %2, 0x989680;\n\t"
            "selp.b32 %0, 1, 0, p;\n\t}"
            : "=r"(done) : "r"(a), "r"(parity) : "memory");
    } while (!done);
}
__device__ __forceinline__ void cluster_sync2() {
    asm volatile("barrier.cluster.arrive.aligned;" ::: "memory");
    asm volatile("barrier.cluster.wait.aligned;" ::: "memory");
}

// column -> (gru row | att row) mapping
__device__ __forceinline__ void colmap(int j, int& row, int& q) {
    row = -1; q = -1;
    if (j < 480) { int m = j % 160; if (m < 150) row = (j / 160) * 150 + m; }
    else if (j < 500) q = j - 480;
}

// ---------------- init ----------------
__global__ void k_init(int N, int E) {
    int stride = gridDim.x * blockDim.x;
    int t0 = blockIdx.x * blockDim.x + threadIdx.x;
    for (int i = t0; i < N; i += stride) { g_child_ready[i] = 0; g_run_of[i] = -1; }
    if (t0 == 0) g_ticket = 0;
}

// ---------------- run table (single block scan) ----------------
__global__ void k_runscan(const int* __restrict__ ed, int E) {
    __shared__ int sflag[1024];
    __shared__ int sbase;
    int tid = threadIdx.x;
    if (tid == 0) sbase = 0;
    __syncthreads();
    for (int chunk = 0; chunk < E; chunk += 1024) {
        int i = chunk + tid;
        int f = 0;
        if (i < E) f = (i == 0) || (ed[2 * i] != ed[2 * i - 2]);
        sflag[tid] = f;
        __syncthreads();
        for (int off = 1; off < 1024; off <<= 1) {
            int v = (tid >= off) ? sflag[tid - off] : 0;
            __syncthreads();
            sflag[tid] += v;
            __syncthreads();
        }
        if (i < E && f) {
            int rid = sbase + sflag[tid] - 1;
            int p = ed[2 * i];
            g_run_start[rid] = i;
            g_run_of[p] = rid;
            g_desig[p] = ed[2 * i + 1];            // first child = chain link
        }
        __syncthreads();
        if (tid == 0) sbase += sflag[1023];
        __syncthreads();
    }
    if (tid == 0) { g_R = sbase; g_run_start[sbase] = E; }
}

// ---------------- parent map + packed child array (after runscan) -----------
__global__ void k_parent(const int* __restrict__ ed, int E) {
    int i = blockIdx.x * blockDim.x + threadIdx.x;
    if (i < E) {
        int c = ed[2 * i + 1];
        g_parent_of[c] = ed[2 * i];
        g_echild[i] = c | ((g_run_of[c] < 0) ? (int)0x80000000 : 0);
    }
    if (i == 0) g_parent_of[0] = -1;
}

// ---------------- chain tops, node index descending (single block scan) -----
__global__ void k_pathscan(int N) {
    __shared__ int sflag[1024];
    __shared__ int sbase;
    int tid = threadIdx.x;
    if (tid == 0) sbase = 0;
    __syncthreads();
    for (int chunk = 0; chunk < N; chunk += 1024) {
        int nr = chunk + tid;
        int n = N - 1 - nr;
        int f = 0;
        if (nr < N && g_run_of[n] >= 0) {          // internal node
            if (n == 0) f = 1;
            else f = (g_desig[g_parent_of[n]] != n) ? 1 : 0;   // not chain-linked
        }
        sflag[tid] = f;
        __syncthreads();
        for (int off = 1; off < 1024; off <<= 1) {
            int v = (tid >= off) ? sflag[tid - off] : 0;
            __syncthreads();
            sflag[tid] += v;
            __syncthreads();
        }
        if (f) g_path_top[sbase + sflag[tid] - 1] = n;
        __syncthreads();
        if (tid == 0) sbase += sflag[1023];
        __syncthreads();
    }
    if (tid == 0) g_P = sbase;
}

// ---------------- weight reshuffles ----------------
// node_W: (450,490), x layout: [word 0..299 | K 300..449 | rel 450..469 | tag 470..489]
__global__ void k_build_big(const float* __restrict__ node_W, const float* __restrict__ node_U,
                            const float* __restrict__ at_Wb,  const float* __restrict__ leaf_W) {
    int idx = blockIdx.x * blockDim.x + threadIdx.x;
    if (idx >= 320 * JPAD) return;
    int i = idx / JPAD, j = idx % JPAD;
    int row, q; colmap(j, row, q);
    float v = 0.f;
    if (row >= 0)      v = (i < 300) ? node_W[row * 490 + i] : node_W[row * 490 + 470 + (i - 300)];
    else if (q >= 0)   v = (i < 300) ? at_Wb[q * 490 + i]    : at_Wb[q * 490 + 470 + (i - 300)];
    g_WcombT[idx] = v;
    g_leafWT[idx] = (row >= 0) ? leaf_W[row * 320 + i] : 0.f;
    if (i < 304) {
        float mv = 0.f;
        if (i < 150) {
            if (row >= 0) mv = node_U[row * 150 + i];
        } else if (i >= 152 && i < 302) {
            int kk = i - 152;
            if (row >= 0)      mv = node_W[row * 490 + 300 + kk];
            else if (q >= 0)   mv = at_Wb[q * 490 + 300 + kk];
        }
        reinterpret_cast<float*>(g_dyn4)[((i >> 2) * JPAD + j) * 4 + (i & 3)] = mv;
    }
    if (i < 160) {
        float kv = 0.f;
        if (i < 150) {
            if (row >= 0)      kv = node_W[row * 490 + 300 + i];
            else if (q >= 0)   kv = at_Wb[q * 490 + 300 + i];
        }
        g_WkT[i * JPAD + j] = kv;
    }
}

__global__ void k_build_small(const float* __restrict__ node_W, const float* __restrict__ at_Wb,
                              const float* __restrict__ node_b, const float* __restrict__ at_bb) {
    int idx = blockIdx.x * blockDim.x + threadIdx.x;
    if (idx < 20 * JPAD) {
        int i = idx / JPAD, j = idx % JPAD;
        int row, q; colmap(j, row, q);
        float v = 0.f;
        if (row >= 0)    v = node_W[row * 490 + 450 + i];
        else if (q >= 0) v = at_Wb[q * 490 + 450 + i];
        g_WrelT[idx] = v;
    } else if (idx < 21 * JPAD) {
        int j = idx - 20 * JPAD;
        int row, q; colmap(j, row, q);
        g_bias[j] = (row >= 0) ? node_b[row] : ((q >= 0) ? at_bb[q] : 0.f);
    }
}

__global__ void k_c0(const float* __restrict__ leaf_U, const float* __restrict__ leaf_h,
                     const float* __restrict__ leaf_b) {
    int j = threadIdx.x;
    if (j >= JPAD) return;
    int row, q; colmap(j, row, q);
    float v = 0.f;
    if (row >= 0) {
        v = leaf_b[row];
        for (int n = 0; n < MEM; n++) v += leaf_U[row * 150 + n] * leaf_h[n];
    }
    g_c0[j] = v;
}

// ---------------- tiled GEMM ----------------
// mode 0: g_stat[n][j]    = [w|tag][n] @ WcombT + bias     (M=N, K=320)
// mode 1: g_leafpre[l][j] = [w|tag][lids[l]] @ leafWT + c0 (M=L, K=320)
// mode 2: g_kpre[lids[l]][j] = K_leaf[l] @ WkT             (M=L, K=160)
#define BM 64
#define BN 64
#define BK 16
__global__ void __launch_bounds__(256) k_gemm(int mode, int M, int Ktot,
                                              const float* __restrict__ w_emb,
                                              const float* __restrict__ tag_emb,
                                              const int* __restrict__ lids) {
    __shared__ float As[BK][BM + 4];
    __shared__ float Bs[BK][BN];
    const float* B = (mode == 0) ? g_WcombT : ((mode == 1) ? g_leafWT : g_WkT);
    int tid = threadIdx.x;
    int tx = tid & 15, ty = tid >> 4;
    int m0 = blockIdx.x * BM, j0 = blockIdx.y * BN;
    int ka = tid & 15, ma = tid >> 4;
    int jb = tid & 63, kb = tid >> 6;
    float acc[4][4] = {};
    for (int k0 = 0; k0 < Ktot; k0 += BK) {
        #pragma unroll
        for (int it = 0; it < 4; it++) {
            int r = m0 + ma + 16 * it;
            if (r >= M) r = M - 1;
            int row = (mode >= 1) ? lids[r] : r;
            int i = k0 + ka;
            float av;
            if (mode == 2) av = (i < 150) ? g_state[row * MEM + i] : 0.f;
            else av = (i < 300) ? w_emb[row * 300 + i] : tag_emb[row * 20 + (i - 300)];
            As[ka][ma + 16 * it] = av;
        }
        #pragma unroll
        for (int it = 0; it < 4; it++)
            Bs[kb + 4 * it][jb] = B[(k0 + kb + 4 * it) * JPAD + (j0 + jb)];
        __syncthreads();
        #pragma unroll
        for (int k = 0; k < BK; k++) {
            float4 a4 = *(const float4*)&As[k][ty * 4];
            float4 b4 = *(const float4*)&Bs[k][tx * 4];
            float av[4] = {a4.x, a4.y, a4.z, a4.w};
            float bv[4] = {b4.x, b4.y, b4.z, b4.w};
            #pragma unroll
            for (int mm = 0; mm < 4; mm++)
                #pragma unroll
                for (int jj = 0; jj < 4; jj++)
                    acc[mm][jj] = fmaf(av[mm], bv[jj], acc[mm][jj]);
        }
        __syncthreads();
    }
    #pragma unroll
    for (int mm = 0; mm < 4; mm++) {
        int r = m0 + ty * 4 + mm;
        if (r >= M) continue;
        #pragma unroll
        for (int jj = 0; jj < 4; jj++) {
            int j = j0 + tx * 4 + jj;
            if (mode == 0)      g_stat[r * JPAD + j]    = acc[mm][jj] + g_bias[j];
            else if (mode == 1) g_leafpre[r * JPAD + j] = acc[mm][jj] + g_c0[j];
            else                g_kpre[(size_t)lids[r] * JPAD + j] = acc[mm][jj];
        }
    }
}

// ---------------- rel projection (K=20) ----------------
__global__ void __launch_bounds__(512) k_relpart(const float* __restrict__ rel_emb) {
    int n = blockIdx.x, j = threadIdx.x;
    float acc = 0.f;
    #pragma unroll
    for (int q = 0; q < 20; q++)
        acc = fmaf(g_WrelT[q * JPAD + j], __ldg(&rel_emb[n * 20 + q]), acc);
    g_rel[n * JPAD + j] = acc;
}

// ---------------- leaf epilogue ----------------
__global__ void k_leafcomb(const int* __restrict__ lids, const float* __restrict__ leaf_h, int L) {
    int idx = blockIdx.x * blockDim.x + threadIdx.x;
    if (idx >= L * MEM) return;
    int l = idx / MEM, m = idx % MEM;
    float z  = sigf (g_leafpre[l * JPAD + m]);
    float r  = sigf (g_leafpre[l * JPAD + 160 + m]);
    float ht = tanhf(g_leafpre[l * JPAD + 320 + m]);
    g_state[lids[l] * MEM + m] = r * leaf_h[m] + (1.f - z) * ht;
}

// ---------------- persistent cluster-4 chain kernel, st.async rendezvous ----
// roles 0/1/2: z/r/ht gate CTAs (160 cols); role 3: attention (32 cols)
// warp 5 (tid 160) = dedicated dependency poller, overlaps h-matvec.
// Leafness is static (packed in g_echild) -> leaf children never polled.
__global__ void __launch_bounds__(192, 1) __cluster_dims__(4, 1, 1)
k_edges(const float* __restrict__ at_Wa, const float* __restrict__ at_ba) {
    extern __shared__ char smem[];
    volatile int*   tickbuf = (volatile int*)(smem + OFF_TICKBUF);
    volatile float* sa_sh   = (volatile float*)(smem + OFF_SA);
    float*  gatebuf = (float*)(smem + OFF_GATE);   // [2][480]
    float*  vsm  = (float*)(smem + OFF_VSM);
    float4* vsm4 = (float4*)vsm;
    float4* sw4  = (float4*)(smem + OFF_W);
    uint32_t base = smem_u32(smem);

    int tid = threadIdx.x;
    int role = (int)cluster_rank();
    bool comp = (tid < 160);

    // persistent weight slice into SMEM
    if (role < 3) {
        if (comp) {
            int j0 = role * 160;
            for (int r = 0; r < 76; r++)
                sw4[r * 160 + tid] = g_dyn4[r * JPAD + j0 + tid];
        }
    } else if (tid < 32) {
        for (int r = 38; r < 76; r++)
            sw4[(r - 38) * 32 + tid] = g_dyn4[r * JPAD + 480 + tid];
    }
    if (tid < 4) vsm[150 + (tid >> 1) * 152 + (tid & 1)] = 0.f;  // pads 150,151,302,303
    __syncthreads();

    if (tid == 0) {
        mbar_init(base + OFF_GMB, 1);      mbar_init(base + OFF_GMB + 8, 1);
        mbar_init(base + OFF_TMB, 1);      mbar_init(base + OFF_TMB + 8, 1);
    }
    __syncthreads();
    if (tid == 0) {
        mbar_expect_tx(base + OFF_GMB,     GATE_TX);
        mbar_expect_tx(base + OFF_GMB + 8, GATE_TX);
        mbar_expect_tx(base + OFF_TMB,     4);
        mbar_expect_tx(base + OFF_TMB + 8, 4);
    }
    __syncthreads();

    uint32_t rb0 = mapa_rank(base, 0), rb1 = mapa_rank(base, 1);
    uint32_t rb2 = mapa_rank(base, 2), rb3 = mapa_rank(base, 3);

    float ba = 0.f, wa = 0.f;
    if (role == 3) { ba = *at_ba; wa = (tid < 20) ? at_Wa[tid] : 0.f; }

    cluster_sync2();                               // all barriers armed cluster-wide

    if (role == 0 && tid == 0) {                   // bootstrap ticket -> slot 0
        int e0 = atomicAdd(&g_ticket, 1);
        st_async_b32(rb0 + OFF_TICKBUF, (uint32_t)e0, rb0 + OFF_TMB);
        st_async_b32(rb1 + OFF_TICKBUF, (uint32_t)e0, rb1 + OFF_TMB);
        st_async_b32(rb2 + OFF_TICKBUF, (uint32_t)e0, rb2 + OFF_TMB);
        st_async_b32(rb3 + OFF_TICKBUF, (uint32_t)e0, rb3 + OFF_TMB);
    }

    int P = g_P;
    int epar = 0;
    uint32_t gph0 = 0, gph1 = 0;
    int tslot = 0; uint32_t tph0 = 0, tph1 = 0;

    while (true) {
        // ---- ticket rendezvous ----
        uint32_t tmbL = base + OFF_TMB + 8u * (uint32_t)tslot;
        mbar_wait(tmbL, tslot ? tph1 : tph0);
        if (tslot) tph1 ^= 1; else tph0 ^= 1;
        int r = tickbuf[tslot];
        __syncthreads();                           // all read before re-arm
        if (tid == 0) mbar_expect_tx(tmbL, 4);
        if (r >= P) break;
        bool sendNext = (role == 0 && tid == 0);
        tslot ^= 1;

        int t = __ldg(&g_path_top[r]);
        int v = t;
        while (true) {
            int d = __ldg(&g_desig[v]);
            if (__ldg(&g_run_of[d]) < 0) break;
            v = d;
        }
        int cache_id = -1;

        while (true) {                             // chain bottom-up
            int rid = __ldg(&g_run_of[v]);
            int es = __ldg(&g_run_start[rid]), ee = __ldg(&g_run_start[rid + 1]);

            float statv = 0.f;
            if (role < 3) { if (comp) statv = __ldg(&g_stat[(size_t)v * JPAD + role * 160 + tid]); }
            else if (tid < 32) statv = __ldg(&g_stat[(size_t)v * JPAD + 480 + tid]);

            // prefetch first edge of run
            int ce = __ldg(&g_echild[es]);
            int c = ce & 0x7fffffff;
            bool cleaf = (ce < 0);
            float relv = 0.f, kprev = 0.f;
            if (role < 3) { if (comp) relv = __ldg(&g_rel[(size_t)c * JPAD + role * 160 + tid]); }
            else if (tid < 32) relv = __ldg(&g_rel[(size_t)c * JPAD + 480 + tid]);
            if (cleaf) {
                if (role < 3) { if (comp) kprev = __ldg(&g_kpre[(size_t)c * JPAD + role * 160 + tid]); }
                else if (tid < 32) kprev = __ldg(&g_kpre[(size_t)c * JPAD + 480 + tid]);
            }

            bool first = true;
            float hreg = 0.f;

            for (int e = es; e < ee; e++) {
                bool cached = (c == cache_id);
                float macc = 0.f;

                // dedicated poller (warp 5) overlaps the h-matvec below
                if (tid == 160 && !cleaf && !cached) {
                    int n = 0;
                    while (!ld_acq(&g_child_ready[c])) { if (++n > 256) __nanosleep(32); }
                }
                if (!first && role < 3 && comp) {
                    const float4* wp = sw4 + tid;
                    #pragma unroll 4
                    for (int r2 = 0; r2 < 38; r2++) {
                        float4 w = wp[r2 * 160]; float4 v4 = vsm4[r2];
                        macc += w.x * v4.x + w.y * v4.y + w.z * v4.z + w.w * v4.w;
                    }
                }
                __syncthreads();                   // join poll + h-matvec

                if (!cleaf) {
                    if (!cached) {
                        if (tid < 150) vsm[152 + tid] = __ldcg(&g_state[c * MEM + tid]);
                        __syncthreads();
                    }
                    if (role < 3) {
                        if (comp) {
                            const float4* wp = sw4 + tid;
                            #pragma unroll 4
                            for (int r2 = 38; r2 < 76; r2++) {
                                float4 w = wp[r2 * 160]; float4 v4 = vsm4[r2];
                                macc += w.x * v4.x + w.y * v4.y + w.z * v4.z + w.w * v4.w;
                            }
                        }
                    } else if (tid < 32) {
                        const float4* wp = sw4 + tid;
                        #pragma unroll 4
                        for (int r2 = 38; r2 < 76; r2++) {
                            float4 w = wp[(r2 - 38) * 32]; float4 v4 = vsm4[r2];
                            macc += w.x * v4.x + w.y * v4.y + w.z * v4.z + w.w * v4.w;
                        }
                    }
                }

                float acc = statv + relv + kprev + macc;   // kprev==0 unless leaf

                // ---- deliver gates / attention scalar via st.async ----
                uint32_t boff = (uint32_t)OFF_GMB + 8u * (uint32_t)epar;
                if (role < 3) {
                    if (tid < 150) {
                        float gv = (role == 2) ? tanhf(acc) : sigf(acc);
                        uint32_t u = __float_as_uint(gv);
                        uint32_t doff = (uint32_t)OFF_GATE
                                      + (uint32_t)(epar * 480 + role * 160 + tid) * 4u;
                        st_async_b32(rb0 + doff, u, rb0 + boff);
                        st_async_b32(rb1 + doff, u, rb1 + boff);
                        st_async_b32(rb2 + doff, u, rb2 + boff);
                        st_async_b32(rb3 + doff, u, rb3 + boff);
                    }
                } else {
                    float av = (tid < 20) ? wa * tanhf(acc) : 0.f;
                    if (tid < 32) {
                        #pragma unroll
                        for (int o = 16; o; o >>= 1) av += __shfl_down_sync(0xffffffffu, av, o);
                        if (tid == 0) {
                            float a = sigf(av + ba);
                            uint32_t u = __float_as_uint(a);
                            uint32_t doff = (uint32_t)OFF_SA + 4u * (uint32_t)epar;
                            st_async_b32(rb0 + doff, u, rb0 + boff);
                            st_async_b32(rb1 + doff, u, rb1 + boff);
                            st_async_b32(rb2 + doff, u, rb2 + boff);
                            st_async_b32(rb3 + doff, u, rb3 + boff);
                        }
                    }
                }

                // ---- prefetch next edge (loads fly during the gate wait) ----
                int cnext = 0; bool cleafn = false;
                float relvn = 0.f, kprevn = 0.f;
                if (e + 1 < ee) {
                    int ce2 = __ldg(&g_echild[e + 1]);
                    cnext = ce2 & 0x7fffffff;
                    cleafn = (ce2 < 0);
                    if (role < 3) { if (comp) relvn = __ldg(&g_rel[(size_t)cnext * JPAD + role * 160 + tid]); }
                    else if (tid < 32) relvn = __ldg(&g_rel[(size_t)cnext * JPAD + 480 + tid]);
                    if (cleafn) {
                        if (role < 3) { if (comp) kprevn = __ldg(&g_kpre[(size_t)cnext * JPAD + role * 160 + tid]); }
                        else if (tid < 32) kprevn = __ldg(&g_kpre[(size_t)cnext * JPAD + 480 + tid]);
                    }
                }

                // ---- local rendezvous: wait own gate mbarrier ----
                uint32_t gmbL = base + boff;
                mbar_wait(gmbL, epar ? gph1 : gph0);
                if (epar) gph1 ^= 1; else gph0 ^= 1;

                // local combine (every CTA keeps its own h copy)
                float a = sa_sh[epar];
                if (tid < 150) {
                    const float* gb = gatebuf + epar * 480;
                    float z = gb[tid], r_ = gb[160 + tid], ht = gb[320 + tid];
                    float h = first ? 0.f : vsm[tid];
                    float m = r_ * h + (1.f - z) * ht;
                    hreg = a * m + (1.f - a) * h;
                    vsm[tid] = hreg;
                }
                __syncthreads();                   // gates consumed by all threads
                if (tid == 0) mbar_expect_tx(gmbL, GATE_TX);   // re-arm for edge+2
                if (sendNext) {                    // after first rendezvous of chain
                    int rn = atomicAdd(&g_ticket, 1);
                    uint32_t tdoff = (uint32_t)OFF_TICKBUF + 4u * (uint32_t)tslot;
                    uint32_t tboff = (uint32_t)OFF_TMB + 8u * (uint32_t)tslot;
                    st_async_b32(rb0 + tdoff, (uint32_t)rn, rb0 + tboff);
                    st_async_b32(rb1 + tdoff, (uint32_t)rn, rb1 + tboff);
                    st_async_b32(rb2 + tdoff, (uint32_t)rn, rb2 + tboff);
                    st_async_b32(rb3 + tdoff, (uint32_t)rn, rb3 + tboff);
                    sendNext = false;
                }
                first = false;
                epar ^= 1;
                c = cnext; cleaf = cleafn; relv = relvn; kprev = kprevn;
            }

            if (v == t) {                          // chain top: publish + release
                if (role == 3) {
                    if (tid < 150) g_state[v * MEM + tid] = hreg;
                    __threadfence();
                    __syncthreads();
                    if (tid == 0) st_rel(&g_child_ready[v], 1);
                }
                break;
            }
            // chain transition: parent's first edge consumes K[v] from SMEM
            if (tid < 150) vsm[152 + tid] = hreg;
            __syncthreads();
            cache_id = v;
            v = __ldg(&g_parent_of[v]);
        }
    }
    cluster_sync2();
}

__global__ void k_out(float* __restrict__ out) {
    int m = threadIdx.x;
    if (m < MEM) out[m] = g_state[m];
}

// ---------------- launch ----------------
extern "C" void kernel_launch(void* const* d_in, const int* in_sizes, int n_in,
                              void* d_out, int out_size) {
    const float* w_emb   = (const float*)d_in[0];
    const float* tag_emb = (const float*)d_in[1];
    const float* rel_emb = (const float*)d_in[2];
    const float* leaf_h  = (const float*)d_in[3];
    const float* leaf_W  = (const float*)d_in[4];
    const float* leaf_U  = (const float*)d_in[5];
    const float* leaf_b  = (const float*)d_in[6];
    const float* node_W  = (const float*)d_in[7];
    const float* node_U  = (const float*)d_in[8];
    const float* node_b  = (const float*)d_in[9];
    const float* at_Wb   = (const float*)d_in[10];
    const float* at_bb   = (const float*)d_in[11];
    const float* at_Wa   = (const float*)d_in[12];
    const float* at_ba   = (const float*)d_in[13];
    const int*   edges   = (const int*)d_in[14];
    const int*   lids    = (const int*)d_in[15];

    int N = in_sizes[0] / 300;
    int E = in_sizes[14] / 2;
    int L = in_sizes[15];

    cudaFuncSetAttribute(k_edges, cudaFuncAttributeMaxDynamicSharedMemorySize, EDGE_SMEM);

    k_init<<<64, 256>>>(N, E);
    k_runscan<<<1, 1024>>>(edges, E);
    k_parent<<<(E + 255) / 256, 256>>>(edges, E);
    k_pathscan<<<1, 1024>>>(N);
    k_build_big<<<(320 * JPAD + 255) / 256, 256>>>(node_W, node_U, at_Wb, leaf_W);
    k_build_small<<<(21 * JPAD + 255) / 256, 256>>>(node_W, at_Wb, node_b, at_bb);
    k_c0<<<1, 512>>>(leaf_U, leaf_h, leaf_b);
    k_gemm<<<dim3((N + BM - 1) / BM, JPAD / BN), 256>>>(0, N, 320, w_emb, tag_emb, lids);
    k_gemm<<<dim3((L + BM - 1) / BM, JPAD / BN), 256>>>(1, L, 320, w_emb, tag_emb, lids);
    k_relpart<<<N, 512>>>(rel_emb);
    k_leafcomb<<<(L * MEM + 255) / 256, 256>>>(lids, leaf_h, L);
    k_gemm<<<dim3((L + BM - 1) / BM, JPAD / BN), 256>>>(2, L, 160, w_emb, tag_emb, lids);
    k_edges<<<4 * NCLUST, 192, EDGE_SMEM>>>(at_Wa, at_ba);
    k_out<<<1, 256>>>((float*)d_out);
}